// round 6
// baseline (speedup 1.0000x reference)
#include <cuda_runtime.h>
#include <cuda_bf16.h>
#include <math.h>

#define NN 100000      // nodes
#define NE 1000000     // edges
#define F0 58
#define F1 300
#define F2 100
#define NB 98          // ceil(NN / 1024) scan blocks

// ---------------- device scratch (allocation-free rule: static globals) ----
__device__ int   g_indeg[NN];
__device__ float g_dis[NN];
__device__ int   g_row[NE];
__device__ int   g_col[NE];
__device__ int   g_soff[NN + 1];
__device__ int   g_cursor[NN];
__device__ int   g_bsum[NB];
__device__ uint2 g_sedge[NE];                  // packed {row_bits, norm_bits}
__device__ float g_agg1[(size_t)NN * F0];      // 23.2 MB
__device__ float g_h1  [(size_t)NN * F1];      // 120  MB
__device__ float g_h2p [(size_t)NN * F2];      // 40   MB
__device__ float g_agg2[(size_t)NN * F2];      // 40   MB
__device__ float g_h3p [NN];

// ---------------- graph prep ----------------
__global__ void k_zero_indeg() {
    int v = blockIdx.x * blockDim.x + threadIdx.x;
    if (v < NN) g_indeg[v] = 0;
}

// edge_index is int32 on device (JAX x64 disabled coerces int64->int32)
__global__ void k_edge_prep(const int* __restrict__ ei) {
    int e = blockIdx.x * blockDim.x + threadIdx.x;
    if (e >= NE) return;
    int r = ei[e];
    int c = ei[NE + e];
    g_row[e] = r;
    g_col[e] = c;
    atomicAdd(&g_indeg[c], 1);
}

__global__ void k_dis() {
    int v = blockIdx.x * blockDim.x + threadIdx.x;
    if (v < NN) g_dis[v] = rsqrtf((float)(g_indeg[v] + 1));   // +1 self-loop
}

// phase 1: per-block local exclusive scan (1024 elems/block) + block total
__global__ void k_scan_local() {
    __shared__ int warp_sums[32];
    const int tid = threadIdx.x;
    const int v = blockIdx.x * 1024 + tid;
    int val = (v < NN) ? g_indeg[v] : 0;
    int x = val;
    #pragma unroll
    for (int o = 1; o < 32; o <<= 1) {
        int y = __shfl_up_sync(0xffffffffu, x, o);
        if ((tid & 31) >= o) x += y;
    }
    if ((tid & 31) == 31) warp_sums[tid >> 5] = x;
    __syncthreads();
    if (tid < 32) {
        int y = warp_sums[tid];
        #pragma unroll
        for (int o = 1; o < 32; o <<= 1) {
            int z = __shfl_up_sync(0xffffffffu, y, o);
            if (tid >= o) y += z;
        }
        warp_sums[tid] = y;
    }
    __syncthreads();
    int warp_prefix = (tid >= 32) ? warp_sums[(tid >> 5) - 1] : 0;
    if (v < NN) g_soff[v] = x + warp_prefix - val;   // local exclusive
    if (tid == 0) g_bsum[blockIdx.x] = warp_sums[31];
}

// phase 2: tiny exclusive scan of NB block sums (+ grand total to g_soff[NN])
__global__ void k_scan_bsum() {
    if (threadIdx.x == 0) {
        int run = 0;
        for (int b = 0; b < NB; b++) {
            int t = g_bsum[b];
            g_bsum[b] = run;
            run += t;
        }
        g_soff[NN] = run;
    }
}

// phase 3: add block offsets; init cursors
__global__ void k_scan_add() {
    int v = blockIdx.x * 1024 + threadIdx.x;
    if (v >= NN) return;
    int s = g_soff[v] + g_bsum[blockIdx.x];
    g_soff[v] = s;
    g_cursor[v] = s;
}

__global__ void k_scatter() {
    int e = blockIdx.x * blockDim.x + threadIdx.x;
    if (e >= NE) return;
    int r = g_row[e];
    int c = g_col[e];
    int pos = atomicAdd(&g_cursor[c], 1);
    float nrm = g_dis[r] * g_dis[c];
    g_sedge[pos] = make_uint2((unsigned)r, __float_as_uint(nrm));
}

// ---------------- CSR aggregation: dst[v,:] = dis^2*src[v,:] + sum edges ----
template <int F>
__global__ void k_agg_csr(const float* __restrict__ src, float* __restrict__ dst) {
    int gtid = blockIdx.x * blockDim.x + threadIdx.x;
    int v    = gtid >> 5;
    int lane = gtid & 31;
    if (v >= NN) return;

    constexpr int NA = (F + 31) / 32;
    float acc[NA];
    float d = g_dis[v];
    const float* selfp = src + (size_t)v * F;
    #pragma unroll
    for (int i = 0; i < NA; i++) {
        int f = lane + 32 * i;
        acc[i] = (f < F) ? d * d * selfp[f] : 0.f;
    }

    int b  = g_soff[v];
    int e2 = g_soff[v + 1];
    for (int j = b; j < e2; j++) {
        uint2 pe = g_sedge[j];
        const float* sp = src + (size_t)pe.x * F;
        float w = __uint_as_float(pe.y);
        #pragma unroll
        for (int i = 0; i < NA; i++) {
            int f = lane + 32 * i;
            if (f < F) acc[i] += w * sp[f];
        }
    }

    float* dp = dst + (size_t)v * F;
    #pragma unroll
    for (int i = 0; i < NA; i++) {
        int f = lane + 32 * i;
        if (f < F) dp[f] = acc[i];
    }
}

// ---------------- GEMM with packed f32x2 FMA (FFMA2) ----------------------
// C[M,N] = A[M,K] @ B[K,N] (+bias)(+relu)
// Accumulators packed along M (pairs of rows -> broadcast LDS.64 A fragments).
// B scalar in smem, word-swizzled; dup'd into f32x2 pairs in registers.
// TM=8 x TN=4 microtile: 16 u64 acc = 32 regs -> no spill at any occupancy.
#define FMA2(d, a, b) \
    asm("fma.rn.f32x2 %0, %1, %2, %0;" : "+l"(d) : "l"(a), "l"(b))
#define PACK2(d, s) \
    asm("mov.b64 %0, {%1, %1};" : "=l"(d) : "r"(s))

template <int BM, int BN, int BK, int TM, int TN, int NT, int MINB,
          bool BIAS, bool RELU>
__global__ void __launch_bounds__(NT, MINB)
k_gemm2(const float* __restrict__ A, const float* __restrict__ B,
        const float* __restrict__ bias, float* __restrict__ C,
        int M, int N, int K) {
    __shared__ __align__(16) float As[BK][BM + 2];
    __shared__ float Bs[BK][BN];                 // scalar, word-swizzled
    const int tid = threadIdx.x;
    const int tx  = tid % (BN / TN);
    const int ty  = tid / (BN / TN);
    const int brow = blockIdx.y * BM;
    const int bcol = blockIdx.x * BN;

    unsigned long long acc[TM / 2][TN];
    #pragma unroll
    for (int i = 0; i < TM / 2; i++)
        #pragma unroll
        for (int j = 0; j < TN; j++) acc[i][j] = 0ull;

    for (int k0 = 0; k0 < K; k0 += BK) {
        // A fill: consecutive lanes -> consecutive k -> coalesced 128B rows
        #pragma unroll 4
        for (int i = tid; i < BM * BK; i += NT) {
            int m = i / BK, k = i % BK;
            int gm = brow + m, gk = k0 + k;
            As[k][m] = (gm < M && gk < K) ? A[(size_t)gm * K + gk] : 0.f;
        }
        // B fill, swizzle w(n) = (n>>2) + (n&3)*(BN/4)
        #pragma unroll 4
        for (int i = tid; i < BK * BN; i += NT) {
            int k = i / BN, n = i % BN;
            int gk = k0 + k, gn = bcol + n;
            Bs[k][(n >> 2) + (n & 3) * (BN / 4)] =
                (gk < K && gn < N) ? B[(size_t)gk * N + gn] : 0.f;
        }
        __syncthreads();

        #pragma unroll
        for (int k = 0; k < BK; k++) {
            unsigned long long a2[TM / 2], b2[TN];
            #pragma unroll
            for (int i = 0; i < TM / 2; i++)
                a2[i] = *(const unsigned long long*)&As[k][ty * TM + 2 * i];
            #pragma unroll
            for (int j = 0; j < TN; j++) {
                int n = tx * TN + j;
                unsigned bv = __float_as_uint(Bs[k][(n >> 2) + (n & 3) * (BN / 4)]);
                PACK2(b2[j], bv);
            }
            #pragma unroll
            for (int i = 0; i < TM / 2; i++)
                #pragma unroll
                for (int j = 0; j < TN; j++)
                    FMA2(acc[i][j], a2[i], b2[j]);
        }
        __syncthreads();
    }

    #pragma unroll
    for (int i = 0; i < TM / 2; i++) {
        int gm0 = brow + ty * TM + 2 * i;
        #pragma unroll
        for (int j = 0; j < TN; j++) {
            int gn = bcol + tx * TN + j;
            if (gn >= N) continue;
            float lo = __uint_as_float((unsigned)(acc[i][j] & 0xffffffffull));
            float hi = __uint_as_float((unsigned)(acc[i][j] >> 32));
            if (BIAS) { float bb = bias[gn]; lo += bb; hi += bb; }
            if (RELU) { lo = fmaxf(lo, 0.f); hi = fmaxf(hi, 0.f); }
            if (gm0 < M)     C[(size_t)gm0 * N + gn]       = lo;
            if (gm0 + 1 < M) C[(size_t)(gm0 + 1) * N + gn] = hi;
        }
    }
}

// ---------------- layer-3 fused dot: h3p[v] = relu(agg2[v,:]+b2) . W3 -----
__global__ void k_dot3(const float* __restrict__ b2, const float* __restrict__ W3) {
    int gtid = blockIdx.x * blockDim.x + threadIdx.x;
    int v    = gtid >> 5;
    int lane = gtid & 31;
    if (v >= NN) return;
    const float* a = g_agg2 + (size_t)v * F2;
    float s = 0.f;
    for (int f = lane; f < F2; f += 32)
        s += fmaxf(a[f] + b2[f], 0.f) * W3[f];
    #pragma unroll
    for (int o = 16; o > 0; o >>= 1)
        s += __shfl_xor_sync(0xffffffffu, s, o);
    if (lane == 0) g_h3p[v] = s;
}

// out[v] = dis^2*h3p[v] + sum_in norm*h3p[row] + b3   (CSR, no atomics)
__global__ void k_out_csr(float* __restrict__ out, const float* __restrict__ b3) {
    int v = blockIdx.x * blockDim.x + threadIdx.x;
    if (v >= NN) return;
    float d = g_dis[v];
    float s = d * d * g_h3p[v];
    int b  = g_soff[v];
    int e2 = g_soff[v + 1];
    for (int j = b; j < e2; j++) {
        uint2 pe = g_sedge[j];
        s += __uint_as_float(pe.y) * g_h3p[pe.x];
    }
    out[v] = s + b3[0];
}

// ---------------- launch ----------------
extern "C" void kernel_launch(void* const* d_in, const int* in_sizes, int n_in,
                              void* d_out, int out_size) {
    const float* x  = (const float*)d_in[0];
    const int*   ei = (const int*)d_in[1];
    const float* W1 = (const float*)d_in[2];
    const float* b1 = (const float*)d_in[3];
    const float* W2 = (const float*)d_in[4];
    const float* b2 = (const float*)d_in[5];
    const float* W3 = (const float*)d_in[6];
    const float* b3 = (const float*)d_in[7];
    float* out = (float*)d_out;

    const int T = 256;
    float* agg1 = nullptr; cudaGetSymbolAddress((void**)&agg1, g_agg1);
    float* h1   = nullptr; cudaGetSymbolAddress((void**)&h1,   g_h1);
    float* h2p  = nullptr; cudaGetSymbolAddress((void**)&h2p,  g_h2p);
    float* agg2 = nullptr; cudaGetSymbolAddress((void**)&agg2, g_agg2);

    // CSR build (parallel 3-phase scan)
    k_zero_indeg<<<(NN + T - 1) / T, T>>>();
    k_edge_prep<<<(NE + T - 1) / T, T>>>(ei);
    k_dis<<<(NN + T - 1) / T, T>>>();
    k_scan_local<<<NB, 1024>>>();
    k_scan_bsum<<<1, 32>>>();
    k_scan_add<<<NB, 1024>>>();
    k_scatter<<<(NE + T - 1) / T, T>>>();

    const unsigned aggGrid = (unsigned)(((long long)NN * 32 + T - 1) / T);

    // Layer 1: aggregate x (58 feats) first, then GEMM(+bias+relu)
    k_agg_csr<F0><<<aggGrid, T>>>(x, agg1);
    {
        dim3 grid((F1 + 63) / 64, (NN + 127) / 128);
        k_gemm2<128, 64, 32, 8, 4, 256, 2, true, true>
            <<<grid, 256>>>(agg1, W1, b1, h1, NN, F1, F0);
    }

    // Layer 2: GEMM first (300->100), then aggregate 100 feats
    {
        dim3 grid(1, (NN + 127) / 128);   // N=100 fits one 128-col block
        k_gemm2<128, 128, 32, 8, 4, 512, 1, false, false>
            <<<grid, 512>>>(h1, W2, nullptr, h2p, NN, F2, F1);
    }
    k_agg_csr<F2><<<aggGrid, T>>>(h2p, agg2);

    // Layer 3: fused bias2+relu+dot(W3), then CSR aggregation to output
    k_dot3<<<aggGrid, T>>>(b2, W3);
    k_out_csr<<<(NN + T - 1) / T, T>>>(out, b3);

    (void)in_sizes; (void)n_in; (void)out_size;
}

// round 8
// speedup vs baseline: 1.3904x; 1.3904x over previous
#include <cuda_runtime.h>
#include <cuda_bf16.h>
#include <math.h>
#include <stdint.h>

// tcgen05 is only legal on arch-specific targets (sm_103a). The harness also
// runs a plain compute_103 PTX pass; gate the tensor kernels so that pass
// compiles a stub (never executed — exact sm_103a cubin always wins).
#if defined(__CUDA_ARCH_FEAT_SM103_ALL) || defined(__CUDA_ARCH_SPECIFIC__) || defined(__CUDA_ARCH_FAMILY_SPECIFIC__)
#define HAS_TCGEN05 1
#else
#define HAS_TCGEN05 0
#endif

#define NN 100000      // nodes
#define NE 1000000     // edges
#define F0 58
#define F1 300
#define F2 100
#define NB 98          // ceil(NN / 1024) scan blocks
#define MTILES 782     // ceil(NN / 128)
#define NNP (MTILES * 128)   // 100096 padded rows

// tensor-layer padded dims
#define L1_KP 64       // K: 58 -> 64
#define L1_NP 304      // N: 300 -> 304
#define L2_KP 320      // K: 300 -> 320
#define L2_NP 104      // N: 100 -> 104

// ---------------- device scratch (allocation-free rule: static globals) ----
__device__ int      g_indeg[NN];
__device__ float    g_dis[NN];
__device__ int      g_row[NE];
__device__ int      g_col[NE];
__device__ int      g_soff[NN + 1];
__device__ int      g_cursor[NN];
__device__ int      g_bsum[NB];
__device__ uint2    g_sedge[NE];
__device__ float    g_agg1[(size_t)NN * F0];
__device__ unsigned g_h1hi[(size_t)NNP * 160];   // bf16 hi pairs, row = 320 bf16
__device__ unsigned g_h1lo[(size_t)NNP * 160];   // bf16 lo pairs
__device__ float    g_h2p [(size_t)NN * F2];
__device__ float    g_agg2[(size_t)NN * F2];
__device__ float    g_h3p [NN];
__device__ __nv_bfloat16 g_w1hi[L1_NP * L1_KP];  // atom-linearized W1^T
__device__ __nv_bfloat16 g_w1lo[L1_NP * L1_KP];
__device__ __nv_bfloat16 g_w2hi[L2_NP * L2_KP];
__device__ __nv_bfloat16 g_w2lo[L2_NP * L2_KP];

// ---------------- PTX helpers ----------------
__device__ __forceinline__ uint32_t smem_to_u32(const void* p) {
    uint32_t a;
    asm("{ .reg .u64 t; cvta.to.shared.u64 t, %1; cvt.u32.u64 %0, t; }"
        : "=r"(a) : "l"(p));
    return a;
}

#if HAS_TCGEN05
__device__ __forceinline__ uint32_t elect_one_pred() {
    uint32_t pred;
    asm volatile(
        "{\n\t.reg .pred p;\n\t"
        "elect.sync _|p, 0xFFFFFFFF;\n\t"
        "selp.b32 %0, 1, 0, p;\n\t}"
        : "=r"(pred));
    return pred;
}
#define TCGEN05_ALLOC(saddr, n) \
    asm volatile("tcgen05.alloc.cta_group::1.sync.aligned.shared::cta.b32 [%0], %1;" \
                 :: "r"((uint32_t)(saddr)), "r"((uint32_t)(n)) : "memory")
#define TCGEN05_RELINQ() \
    asm volatile("tcgen05.relinquish_alloc_permit.cta_group::1.sync.aligned;")
#define TCGEN05_DEALLOC(t, n) \
    asm volatile("tcgen05.dealloc.cta_group::1.sync.aligned.b32 %0, %1;" :: "r"(t), "r"((uint32_t)(n)))
#define TCGEN05_COMMIT(mbar) \
    asm volatile("tcgen05.commit.cta_group::1.mbarrier::arrive::one.shared::cluster.b64 [%0];" \
                 :: "r"((uint32_t)(mbar)) : "memory")
#define TCGEN05_FENCE_AFTER() asm volatile("tcgen05.fence::after_thread_sync;" ::: "memory")
#define TCGEN05_WAIT_LD()     asm volatile("tcgen05.wait::ld.sync.aligned;" ::: "memory")
#define FENCE_ASYNC()         asm volatile("fence.proxy.async.shared::cta;" ::: "memory")
#define MBARRIER_INIT(mbar, cnt) \
    asm volatile("mbarrier.init.shared.b64 [%0], %1;" :: "r"((uint32_t)(mbar)), "r"((uint32_t)(cnt)) : "memory")
#define MBARRIER_INVAL(mbar) \
    asm volatile("mbarrier.inval.shared.b64 [%0];" :: "r"((uint32_t)(mbar)) : "memory")

__device__ __forceinline__ void mbar_wait(uint32_t mbar, uint32_t parity) {
    uint32_t done;
    asm volatile(
        "{\n\t.reg .pred p;\n\t"
        "mbarrier.try_wait.parity.acquire.cta.shared::cta.b64 p, [%1], %2;\n\t"
        "selp.b32 %0, 1, 0, p;\n\t}"
        : "=r"(done) : "r"(mbar), "r"(parity) : "memory");
    if (!done) {
        asm volatile(
            "{\n\t.reg .pred P1;\n\t"
            "WAIT_LOOP_%=:\n\t"
            "mbarrier.try_wait.parity.acquire.cta.shared::cta.b64 P1, [%0], %1, 0x989680;\n\t"
            "@P1 bra.uni WAIT_DONE_%=;\n\t"
            "bra.uni WAIT_LOOP_%=;\n\t"
            "WAIT_DONE_%=:\n\t}"
            :: "r"(mbar), "r"(parity) : "memory");
    }
}

#define TCGEN05_LD_X32(r, ta) \
    asm volatile( \
        "tcgen05.ld.sync.aligned.32x32b.x32.b32 " \
        "{%0, %1, %2, %3, %4, %5, %6, %7, " \
        " %8, %9, %10, %11, %12, %13, %14, %15, " \
        " %16, %17, %18, %19, %20, %21, %22, %23, " \
        " %24, %25, %26, %27, %28, %29, %30, %31}, [%32];" \
        : "=r"((r)[0]),  "=r"((r)[1]),  "=r"((r)[2]),  "=r"((r)[3]), \
          "=r"((r)[4]),  "=r"((r)[5]),  "=r"((r)[6]),  "=r"((r)[7]), \
          "=r"((r)[8]),  "=r"((r)[9]),  "=r"((r)[10]), "=r"((r)[11]), \
          "=r"((r)[12]), "=r"((r)[13]), "=r"((r)[14]), "=r"((r)[15]), \
          "=r"((r)[16]), "=r"((r)[17]), "=r"((r)[18]), "=r"((r)[19]), \
          "=r"((r)[20]), "=r"((r)[21]), "=r"((r)[22]), "=r"((r)[23]), \
          "=r"((r)[24]), "=r"((r)[25]), "=r"((r)[26]), "=r"((r)[27]), \
          "=r"((r)[28]), "=r"((r)[29]), "=r"((r)[30]), "=r"((r)[31]) \
        : "r"(ta))
#define TCGEN05_LD_X16(r, ta) \
    asm volatile( \
        "tcgen05.ld.sync.aligned.32x32b.x16.b32 " \
        "{%0, %1, %2, %3, %4, %5, %6, %7, " \
        " %8, %9, %10, %11, %12, %13, %14, %15}, [%16];" \
        : "=r"((r)[0]),  "=r"((r)[1]),  "=r"((r)[2]),  "=r"((r)[3]), \
          "=r"((r)[4]),  "=r"((r)[5]),  "=r"((r)[6]),  "=r"((r)[7]), \
          "=r"((r)[8]),  "=r"((r)[9]),  "=r"((r)[10]), "=r"((r)[11]), \
          "=r"((r)[12]), "=r"((r)[13]), "=r"((r)[14]), "=r"((r)[15]) \
        : "r"(ta))
#define TCGEN05_LD_X8(r, ta) \
    asm volatile( \
        "tcgen05.ld.sync.aligned.32x32b.x8.b32 " \
        "{%0, %1, %2, %3, %4, %5, %6, %7}, [%8];" \
        : "=r"((r)[0]), "=r"((r)[1]), "=r"((r)[2]), "=r"((r)[3]), \
          "=r"((r)[4]), "=r"((r)[5]), "=r"((r)[6]), "=r"((r)[7]) \
        : "r"(ta))

// SS-mode cg1 bf16 MMA: D(TMEM) += A(smem desc) * B(smem desc)^T
__device__ __forceinline__ void mma_f16_ss(uint32_t d_tmem, uint64_t a_desc,
                                           uint64_t b_desc, uint32_t idesc,
                                           uint32_t en) {
    asm volatile(
        "{\n\t.reg .pred p;\n\t"
        "setp.ne.u32 p, %4, 0;\n\t"
        "tcgen05.mma.cta_group::1.kind::f16 [%0], %1, %2, %3, {%5, %5, %5, %5}, p;\n\t}"
        :: "r"(d_tmem), "l"(a_desc), "l"(b_desc), "r"(idesc), "r"(en), "r"(0u)
        : "memory");
}
#endif  // HAS_TCGEN05

static constexpr uint64_t SMEM_DESC_BASE_SW128 =
    (uint64_t(2) << 61) | (uint64_t(1) << 46) | (uint64_t(64) << 32) | (uint64_t(1) << 16);
#define MAKE_SMEM_DESC(a) (SMEM_DESC_BASE_SW128 | ((uint64_t)((a) >> 4) & 0x3FFF))
#define SWZ128(b) ((b) ^ (((b) >> 3) & 0x70))

// idesc: dtype F32(bit4) | atype BF16(bit7) | btype BF16(bit10) | N/8<<17 | M/16<<24
#define IDESC(NV) ((8u << 24) | (((NV) / 8u) << 17) | 0x490u)

// ---------------- graph prep ----------------
__global__ void k_zero_indeg() {
    int v = blockIdx.x * blockDim.x + threadIdx.x;
    if (v < NN) g_indeg[v] = 0;
}
__global__ void k_edge_prep(const int* __restrict__ ei) {
    int e = blockIdx.x * blockDim.x + threadIdx.x;
    if (e >= NE) return;
    int r = ei[e];
    int c = ei[NE + e];
    g_row[e] = r;
    g_col[e] = c;
    atomicAdd(&g_indeg[c], 1);
}
__global__ void k_dis() {
    int v = blockIdx.x * blockDim.x + threadIdx.x;
    if (v < NN) g_dis[v] = rsqrtf((float)(g_indeg[v] + 1));
}
__global__ void k_scan_local() {
    __shared__ int warp_sums[32];
    const int tid = threadIdx.x;
    const int v = blockIdx.x * 1024 + tid;
    int val = (v < NN) ? g_indeg[v] : 0;
    int x = val;
    #pragma unroll
    for (int o = 1; o < 32; o <<= 1) {
        int y = __shfl_up_sync(0xffffffffu, x, o);
        if ((tid & 31) >= o) x += y;
    }
    if ((tid & 31) == 31) warp_sums[tid >> 5] = x;
    __syncthreads();
    if (tid < 32) {
        int y = warp_sums[tid];
        #pragma unroll
        for (int o = 1; o < 32; o <<= 1) {
            int z = __shfl_up_sync(0xffffffffu, y, o);
            if (tid >= o) y += z;
        }
        warp_sums[tid] = y;
    }
    __syncthreads();
    int warp_prefix = (tid >= 32) ? warp_sums[(tid >> 5) - 1] : 0;
    if (v < NN) g_soff[v] = x + warp_prefix - val;
    if (tid == 0) g_bsum[blockIdx.x] = warp_sums[31];
}
__global__ void k_scan_bsum() {
    if (threadIdx.x == 0) {
        int run = 0;
        for (int b = 0; b < NB; b++) { int t = g_bsum[b]; g_bsum[b] = run; run += t; }
        g_soff[NN] = run;
    }
}
__global__ void k_scan_add() {
    int v = blockIdx.x * 1024 + threadIdx.x;
    if (v >= NN) return;
    int s = g_soff[v] + g_bsum[blockIdx.x];
    g_soff[v] = s;
    g_cursor[v] = s;
}
__global__ void k_scatter() {
    int e = blockIdx.x * blockDim.x + threadIdx.x;
    if (e >= NE) return;
    int r = g_row[e];
    int c = g_col[e];
    int pos = atomicAdd(&g_cursor[c], 1);
    float nrm = g_dis[r] * g_dis[c];
    g_sedge[pos] = make_uint2((unsigned)r, __float_as_uint(nrm));
}

// ---------------- weight prep: transpose + hi/lo split + atom-linearize ---
// B operand layout [Np rows(N), Kp cols(K)], atom = 8n x 64k (1024B), atoms
// ordered atom_row-major then atom_col:  off = (n/8 + (k/64)*(Np/8))*512 + (n%8)*64 + (k%64)
__global__ void k_prep_w(const float* __restrict__ W, __nv_bfloat16* __restrict__ hi,
                         __nv_bfloat16* __restrict__ lo, int K, int N, int Kp, int Np) {
    int idx = blockIdx.x * blockDim.x + threadIdx.x;
    if (idx >= Kp * Np) return;
    int n = idx / Kp, k = idx % Kp;
    float v = (n < N && k < K) ? W[(size_t)k * N + n] : 0.f;
    __nv_bfloat16 h = __float2bfloat16(v);
    __nv_bfloat16 l = __float2bfloat16(v - __bfloat162float(h));
    int off = ((n >> 3) + (k >> 6) * (Np >> 3)) * 512 + (n & 7) * 64 + (k & 63);
    hi[off] = h;
    lo[off] = l;
}

// ---------------- CSR aggregation ----------------
template <int F>
__global__ void k_agg_csr(const float* __restrict__ src, float* __restrict__ dst) {
    int gtid = blockIdx.x * blockDim.x + threadIdx.x;
    int v    = gtid >> 5;
    int lane = gtid & 31;
    if (v >= NN) return;
    constexpr int NA = (F + 31) / 32;
    float acc[NA];
    float d = g_dis[v];
    const float* selfp = src + (size_t)v * F;
    #pragma unroll
    for (int i = 0; i < NA; i++) {
        int f = lane + 32 * i;
        acc[i] = (f < F) ? d * d * selfp[f] : 0.f;
    }
    int b  = g_soff[v];
    int e2 = g_soff[v + 1];
    for (int j = b; j < e2; j++) {
        uint2 pe = g_sedge[j];
        const float* sp = src + (size_t)pe.x * F;
        float w = __uint_as_float(pe.y);
        #pragma unroll
        for (int i = 0; i < NA; i++) {
            int f = lane + 32 * i;
            if (f < F) acc[i] += w * sp[f];
        }
    }
    float* dp = dst + (size_t)v * F;
    #pragma unroll
    for (int i = 0; i < NA; i++) {
        int f = lane + 32 * i;
        if (f < F) dp[f] = acc[i];
    }
}

// ================= Layer-1 tensor GEMM ====================================
// h1 = relu(agg1 @ W1 + b1), output stored directly as bf16 hi/lo [NNP x 320]
#define S1_AHI 1024
#define S1_ALO 17408
#define S1_BHI 33792
#define S1_BLO 72704
#define S1_STH 1024
#define S1_STL 83456
#define SMEM1  165888

__global__ void __launch_bounds__(256, 1)
k_tgemm1(const float* __restrict__ A, const float* __restrict__ b1) {
#if HAS_TCGEN05
    extern __shared__ char smem[];
    uint32_t sb = smem_to_u32(smem);
    int tid = threadIdx.x, wid = tid >> 5, lane = tid & 31;
    int brow = blockIdx.x * 128;

    if (wid == 0) { TCGEN05_ALLOC(sb + 0, 512); TCGEN05_RELINQ(); }
    if (tid == 0) MBARRIER_INIT(sb + 8, 1);
    __syncthreads();
    uint32_t tb = *(volatile uint32_t*)smem;

    // A fill: [128 rows x 64 bf16], SW128, zero-padded k>=F0 / ghost rows
    for (int i = tid; i < 128 * 64; i += 256) {
        int m = i >> 6, k = i & 63;
        int gm = brow + m;
        float v = (gm < NN && k < F0) ? A[(size_t)gm * F0 + k] : 0.f;
        __nv_bfloat16 h = __float2bfloat16(v);
        __nv_bfloat16 l = __float2bfloat16(v - __bfloat162float(h));
        uint32_t sw = SWZ128((uint32_t)((m << 7) + (k << 1)));
        *(__nv_bfloat16*)(smem + S1_AHI + sw) = h;
        *(__nv_bfloat16*)(smem + S1_ALO + sw) = l;
    }
    // B fill: 16B-granule copy with swizzle
    for (int i = tid; i < (L1_NP * L1_KP) / 8; i += 256) {
        uint4 h = ((const uint4*)g_w1hi)[i];
        uint4 l = ((const uint4*)g_w1lo)[i];
        uint32_t sw = SWZ128((uint32_t)(i * 16));
        *(uint4*)(smem + S1_BHI + sw) = h;
        *(uint4*)(smem + S1_BLO + sw) = l;
    }
    FENCE_ASYNC();
    __syncthreads();

    if (wid == 0 && elect_one_pred()) {
        uint64_t ah = MAKE_SMEM_DESC(sb + S1_AHI);
        uint64_t al = MAKE_SMEM_DESC(sb + S1_ALO);
        uint64_t bh = MAKE_SMEM_DESC(sb + S1_BHI);
        uint64_t bl = MAKE_SMEM_DESC(sb + S1_BLO);
        const uint32_t id0 = IDESC(256), id1 = IDESC(48);
        // second N-tile: atoms 32..37 -> +32*1024B = +2048 desc units
        #pragma unroll
        for (int s = 0; s < 4; s++) {
            uint32_t en = (s > 0);
            mma_f16_ss(tb,       ah + 2 * s, bh + 2 * s,        id0, en);
            mma_f16_ss(tb + 256, ah + 2 * s, bh + 2048 + 2 * s, id1, en);
            mma_f16_ss(tb,       ah + 2 * s, bl + 2 * s,        id0, 1);
            mma_f16_ss(tb + 256, ah + 2 * s, bl + 2048 + 2 * s, id1, 1);
            mma_f16_ss(tb,       al + 2 * s, bh + 2 * s,        id0, 1);
            mma_f16_ss(tb + 256, al + 2 * s, bh + 2048 + 2 * s, id1, 1);
        }
        TCGEN05_COMMIT(sb + 8);
    }
    mbar_wait(sb + 8, 0);
    TCGEN05_FENCE_AFTER();
    __syncthreads();     // all MMAs done; smem safe to reuse as staging

    // epilogue: LDTM 304 cols, bias+relu, split bf16, stage as u32 pairs
    uint32_t* sth = (uint32_t*)(smem + S1_STH);
    uint32_t* stl = (uint32_t*)(smem + S1_STL);
    if (wid < 4) {
        int row = wid * 32 + lane;
        #pragma unroll
        for (int g = 0; g < 10; g++) {
            int base = g * 32;
            uint32_t r[32];
            if (g < 9) { TCGEN05_LD_X32(r, tb + base); }
            else       { TCGEN05_LD_X16(r, tb + 288); }
            TCGEN05_WAIT_LD();
            int cnt = (g < 9) ? 32 : 16;
            for (int j = 0; j < cnt; j += 2) {
                int c = base + j;
                float v0 = (c     < F1) ? fmaxf(__uint_as_float(r[j])     + b1[c],     0.f) : 0.f;
                float v1 = (c + 1 < F1) ? fmaxf(__uint_as_float(r[j + 1]) + b1[c + 1], 0.f) : 0.f;
                __nv_bfloat16 h0 = __float2bfloat16(v0);
                __nv_bfloat16 h1b = __float2bfloat16(v1);
                __nv_bfloat16 l0 = __float2bfloat16(v0 - __bfloat162float(h0));
                __nv_bfloat16 l1 = __float2bfloat16(v1 - __bfloat162float(h1b));
                __nv_bfloat162 ph = __halves2bfloat162(h0, h1b);
                __nv_bfloat162 pl = __halves2bfloat162(l0, l1);
                sth[row * 161 + (c >> 1)] = *(uint32_t*)&ph;
                stl[row * 161 + (c >> 1)] = *(uint32_t*)&pl;
            }
        }
        #pragma unroll
        for (int q = 152; q < 160; q++) {   // zero pad cols 304..319
            sth[row * 161 + q] = 0;
            stl[row * 161 + q] = 0;
        }
    }
    __syncthreads();
    // coalesced copy-out (rows always < NNP)
    for (int i = tid; i < 128 * 160; i += 256) {
        int m = i / 160, q = i - m * 160;
        size_t go = (size_t)(brow + m) * 160 + q;
        g_h1hi[go] = sth[m * 161 + q];
        g_h1lo[go] = stl[m * 161 + q];
    }
    __syncthreads();
    if (tid == 0) MBARRIER_INVAL(sb + 8);
    __syncthreads();
    if (wid == 0) TCGEN05_DEALLOC(tb, 512);
#endif
}

// ================= Layer-2 tensor GEMM ====================================
#define S2_AHI 1024
#define S2_ALO 17408
#define S2_BHI 33792
#define S2_BLO 100352
#define SMEM2  166912

__global__ void __launch_bounds__(256, 1)
k_tgemm2(float* __restrict__ Cout) {
#if HAS_TCGEN05
    extern __shared__ char smem[];
    uint32_t sb = smem_to_u32(smem);
    int tid = threadIdx.x, wid = tid >> 5, lane = tid & 31;
    int brow = blockIdx.x * 128;

    if (wid == 0) { TCGEN05_ALLOC(sb + 0, 512); TCGEN05_RELINQ(); }
    if (tid == 0) MBARRIER_INIT(sb + 8, 1);
    __syncthreads();
    uint32_t tb = *(volatile uint32_t*)smem;

    // B fill once: W2 atom-linearized (13 atom-rows, 5 atom-cols)
    for (int i = tid; i < (L2_NP * L2_KP) / 8; i += 256) {
        uint4 h = ((const uint4*)g_w2hi)[i];
        uint4 l = ((const uint4*)g_w2lo)[i];
        uint32_t sw = SWZ128((uint32_t)(i * 16));
        *(uint4*)(smem + S2_BHI + sw) = h;
        *(uint4*)(smem + S2_BLO + sw) = l;
    }

    uint64_t ah = MAKE_SMEM_DESC(sb + S2_AHI);
    uint64_t al = MAKE_SMEM_DESC(sb + S2_ALO);
    uint64_t bh = MAKE_SMEM_DESC(sb + S2_BHI);
    uint64_t bl = MAKE_SMEM_DESC(sb + S2_BLO);
    const uint32_t id = IDESC(104);
    bool first = true;

    for (int c = 0; c < 5; c++) {
        // A chunk fill: rows 0..127, K cols [64c, 64c+64) as uint4 copies
        for (int i = tid; i < 1024; i += 256) {
            int m = i >> 3, q = i & 7;
            size_t gi = (size_t)(brow + m) * 40 + c * 8 + q;   // uint4 index
            uint4 h = ((const uint4*)g_h1hi)[gi];
            uint4 l = ((const uint4*)g_h1lo)[gi];
            uint32_t sw = SWZ128((uint32_t)((m << 7) + (q << 4)));
            *(uint4*)(smem + S2_AHI + sw) = h;
            *(uint4*)(smem + S2_ALO + sw) = l;
        }
        FENCE_ASYNC();
        __syncthreads();

        if (wid == 0 && elect_one_pred()) {
            uint32_t boff = c * 832;   // atom-col stride: 13 atoms * 1024B / 16
            #pragma unroll
            for (int s = 0; s < 4; s++) {
                uint32_t aoff = 2 * s, ko = boff + 2 * s;
                mma_f16_ss(tb, ah + aoff, bh + ko, id, first ? 0u : 1u);
                first = false;
                mma_f16_ss(tb, ah + aoff, bl + ko, id, 1);
                mma_f16_ss(tb, al + aoff, bh + ko, id, 1);
            }
            TCGEN05_COMMIT(sb + 8);
        }
        mbar_wait(sb + 8, (uint32_t)(c & 1));
        __syncthreads();
    }
    TCGEN05_FENCE_AFTER();

    float* stg = (float*)(smem + 1024);
    if (wid < 4) {
        int row = wid * 32 + lane;
        uint32_t r[32];
        #pragma unroll
        for (int g = 0; g < 3; g++) {
            TCGEN05_LD_X32(r, tb + g * 32);
            TCGEN05_WAIT_LD();
            for (int j = 0; j < 32; j++)
                stg[row * 105 + g * 32 + j] = __uint_as_float(r[j]);
        }
        TCGEN05_LD_X8(r, tb + 96);
        TCGEN05_WAIT_LD();
        for (int j = 0; j < 4; j++)      // cols 96..99 (100..103 are pad)
            stg[row * 105 + 96 + j] = __uint_as_float(r[j]);
    }
    __syncthreads();
    for (int i = tid; i < 128 * 100; i += 256) {
        int m = i / 100, cc = i - m * 100;
        int gm = brow + m;
        if (gm < NN) Cout[(size_t)gm * 100 + cc] = stg[m * 105 + cc];
    }
    __syncthreads();
    if (tid == 0) MBARRIER_INVAL(sb + 8);
    __syncthreads();
    if (wid == 0) TCGEN05_DEALLOC(tb, 512);
#endif
}

// ---------------- layer-3 fused dot + output ------------------------------
__global__ void k_dot3(const float* __restrict__ b2, const float* __restrict__ W3) {
    int gtid = blockIdx.x * blockDim.x + threadIdx.x;
    int v    = gtid >> 5;
    int lane = gtid & 31;
    if (v >= NN) return;
    const float* a = g_agg2 + (size_t)v * F2;
    float s = 0.f;
    for (int f = lane; f < F2; f += 32)
        s += fmaxf(a[f] + b2[f], 0.f) * W3[f];
    #pragma unroll
    for (int o = 16; o > 0; o >>= 1)
        s += __shfl_xor_sync(0xffffffffu, s, o);
    if (lane == 0) g_h3p[v] = s;
}
__global__ void k_out_csr(float* __restrict__ out, const float* __restrict__ b3) {
    int v = blockIdx.x * blockDim.x + threadIdx.x;
    if (v >= NN) return;
    float d = g_dis[v];
    float s = d * d * g_h3p[v];
    int b  = g_soff[v];
    int e2 = g_soff[v + 1];
    for (int j = b; j < e2; j++) {
        uint2 pe = g_sedge[j];
        s += __uint_as_float(pe.y) * g_h3p[pe.x];
    }
    out[v] = s + b3[0];
}

// ---------------- launch ----------------
extern "C" void kernel_launch(void* const* d_in, const int* in_sizes, int n_in,
                              void* d_out, int out_size) {
    const float* x  = (const float*)d_in[0];
    const int*   ei = (const int*)d_in[1];
    const float* W1 = (const float*)d_in[2];
    const float* b1 = (const float*)d_in[3];
    const float* W2 = (const float*)d_in[4];
    const float* b2 = (const float*)d_in[5];
    const float* W3 = (const float*)d_in[6];
    const float* b3 = (const float*)d_in[7];
    float* out = (float*)d_out;

    const int T = 256;
    float* agg1 = nullptr; cudaGetSymbolAddress((void**)&agg1, g_agg1);
    float* h2p  = nullptr; cudaGetSymbolAddress((void**)&h2p,  g_h2p);
    float* agg2 = nullptr; cudaGetSymbolAddress((void**)&agg2, g_agg2);
    __nv_bfloat16 *w1h, *w1l, *w2h, *w2l;
    cudaGetSymbolAddress((void**)&w1h, g_w1hi);
    cudaGetSymbolAddress((void**)&w1l, g_w1lo);
    cudaGetSymbolAddress((void**)&w2h, g_w2hi);
    cudaGetSymbolAddress((void**)&w2l, g_w2lo);

    cudaFuncSetAttribute(k_tgemm1, cudaFuncAttributeMaxDynamicSharedMemorySize, SMEM1);
    cudaFuncSetAttribute(k_tgemm2, cudaFuncAttributeMaxDynamicSharedMemorySize, SMEM2);

    // weight prep (graph-independent)
    k_prep_w<<<(L1_NP * L1_KP + T - 1) / T, T>>>(W1, w1h, w1l, F0, F1, L1_KP, L1_NP);
    k_prep_w<<<(L2_NP * L2_KP + T - 1) / T, T>>>(W2, w2h, w2l, F1, F2, L2_KP, L2_NP);

    // CSR build
    k_zero_indeg<<<(NN + T - 1) / T, T>>>();
    k_edge_prep<<<(NE + T - 1) / T, T>>>(ei);
    k_dis<<<(NN + T - 1) / T, T>>>();
    k_scan_local<<<NB, 1024>>>();
    k_scan_bsum<<<1, 32>>>();
    k_scan_add<<<NB, 1024>>>();
    k_scatter<<<(NE + T - 1) / T, T>>>();

    const unsigned aggGrid = (unsigned)(((long long)NN * 32 + T - 1) / T);

    // Layer 1: aggregate (58 feats) -> tensor GEMM(+bias+relu) -> bf16 h1
    k_agg_csr<F0><<<aggGrid, T>>>(x, agg1);
    k_tgemm1<<<MTILES, 256, SMEM1>>>(agg1, b1);

    // Layer 2: tensor GEMM (300->100) -> aggregate (100 feats)
    k_tgemm2<<<MTILES, 256, SMEM2>>>(h2p);
    k_agg_csr<F2><<<aggGrid, T>>>(h2p, agg2);

    // Layer 3
    k_dot3<<<aggGrid, T>>>(b2, W3);
    k_out_csr<<<(NN + T - 1) / T, T>>>(out, b3);

    (void)in_sizes; (void)n_in; (void)out_size;
}

// round 9
// speedup vs baseline: 2.1436x; 1.5417x over previous
#include <cuda_runtime.h>
#include <cuda_bf16.h>
#include <math.h>
#include <stdint.h>

// tcgen05 is only legal on arch-specific targets (sm_103a). The harness also
// runs a plain compute_103 PTX pass; gate the tensor kernels so that pass
// compiles a stub (never executed — exact sm_103a cubin always wins).
#if defined(__CUDA_ARCH_FEAT_SM103_ALL) || defined(__CUDA_ARCH_SPECIFIC__) || defined(__CUDA_ARCH_FAMILY_SPECIFIC__)
#define HAS_TCGEN05 1
#else
#define HAS_TCGEN05 0
#endif

#define NN 100000      // nodes
#define NE 1000000     // edges
#define F0 58
#define F1 300
#define F2 100
#define NB 98          // ceil(NN / 1024) scan blocks
#define MTILES 782     // ceil(NN / 128)

// tensor-layer padded dims
#define L1_KP 64       // K: 58 -> 64
#define L1_NP 304      // N: 300 -> 304
#define L2_KP 320      // K: 300 -> 320
#define L2_NP 104      // N: 100 -> 104

// ---------------- device scratch (allocation-free rule: static globals) ----
__device__ int      g_indeg[NN];
__device__ float    g_dis[NN];
__device__ int      g_row[NE];
__device__ int      g_col[NE];
__device__ int      g_soff[NN + 1];
__device__ int      g_cursor[NN];
__device__ int      g_bsum[NB];
__device__ uint2    g_sedge[NE];
__device__ float    g_agg1[(size_t)NN * F0];
__device__ float    g_h2p [(size_t)NN * F2];
__device__ float    g_agg2[(size_t)NN * F2];
__device__ float    g_h3p [NN];
__device__ __nv_bfloat16 g_w1hi[L1_NP * L1_KP];  // atom-linearized W1^T
__device__ __nv_bfloat16 g_w1lo[L1_NP * L1_KP];
__device__ __nv_bfloat16 g_w2hi[L2_NP * L2_KP];
__device__ __nv_bfloat16 g_w2lo[L2_NP * L2_KP];

// ---------------- PTX helpers ----------------
__device__ __forceinline__ uint32_t smem_to_u32(const void* p) {
    uint32_t a;
    asm("{ .reg .u64 t; cvta.to.shared.u64 t, %1; cvt.u32.u64 %0, t; }"
        : "=r"(a) : "l"(p));
    return a;
}

#if HAS_TCGEN05
__device__ __forceinline__ uint32_t elect_one_pred() {
    uint32_t pred;
    asm volatile(
        "{\n\t.reg .pred p;\n\t"
        "elect.sync _|p, 0xFFFFFFFF;\n\t"
        "selp.b32 %0, 1, 0, p;\n\t}"
        : "=r"(pred));
    return pred;
}
#define TCGEN05_ALLOC(saddr, n) \
    asm volatile("tcgen05.alloc.cta_group::1.sync.aligned.shared::cta.b32 [%0], %1;" \
                 :: "r"((uint32_t)(saddr)), "r"((uint32_t)(n)) : "memory")
#define TCGEN05_RELINQ() \
    asm volatile("tcgen05.relinquish_alloc_permit.cta_group::1.sync.aligned;")
#define TCGEN05_DEALLOC(t, n) \
    asm volatile("tcgen05.dealloc.cta_group::1.sync.aligned.b32 %0, %1;" :: "r"(t), "r"((uint32_t)(n)))
#define TCGEN05_COMMIT(mbar) \
    asm volatile("tcgen05.commit.cta_group::1.mbarrier::arrive::one.shared::cluster.b64 [%0];" \
                 :: "r"((uint32_t)(mbar)) : "memory")
#define TCGEN05_FENCE_AFTER() asm volatile("tcgen05.fence::after_thread_sync;" ::: "memory")
#define TCGEN05_WAIT_LD()     asm volatile("tcgen05.wait::ld.sync.aligned;" ::: "memory")
#define FENCE_ASYNC()         asm volatile("fence.proxy.async.shared::cta;" ::: "memory")
#define MBARRIER_INIT(mbar, cnt) \
    asm volatile("mbarrier.init.shared.b64 [%0], %1;" :: "r"((uint32_t)(mbar)), "r"((uint32_t)(cnt)) : "memory")
#define MBARRIER_INVAL(mbar) \
    asm volatile("mbarrier.inval.shared.b64 [%0];" :: "r"((uint32_t)(mbar)) : "memory")

__device__ __forceinline__ void mbar_wait(uint32_t mbar, uint32_t parity) {
    uint32_t done;
    asm volatile(
        "{\n\t.reg .pred p;\n\t"
        "mbarrier.try_wait.parity.acquire.cta.shared::cta.b64 p, [%1], %2;\n\t"
        "selp.b32 %0, 1, 0, p;\n\t}"
        : "=r"(done) : "r"(mbar), "r"(parity) : "memory");
    if (!done) {
        asm volatile(
            "{\n\t.reg .pred P1;\n\t"
            "WAIT_LOOP_%=:\n\t"
            "mbarrier.try_wait.parity.acquire.cta.shared::cta.b64 P1, [%0], %1, 0x989680;\n\t"
            "@P1 bra.uni WAIT_DONE_%=;\n\t"
            "bra.uni WAIT_LOOP_%=;\n\t"
            "WAIT_DONE_%=:\n\t}"
            :: "r"(mbar), "r"(parity) : "memory");
    }
}

#define TCGEN05_LD_X32(r, ta) \
    asm volatile( \
        "tcgen05.ld.sync.aligned.32x32b.x32.b32 " \
        "{%0, %1, %2, %3, %4, %5, %6, %7, " \
        " %8, %9, %10, %11, %12, %13, %14, %15, " \
        " %16, %17, %18, %19, %20, %21, %22, %23, " \
        " %24, %25, %26, %27, %28, %29, %30, %31}, [%32];" \
        : "=r"((r)[0]),  "=r"((r)[1]),  "=r"((r)[2]),  "=r"((r)[3]), \
          "=r"((r)[4]),  "=r"((r)[5]),  "=r"((r)[6]),  "=r"((r)[7]), \
          "=r"((r)[8]),  "=r"((r)[9]),  "=r"((r)[10]), "=r"((r)[11]), \
          "=r"((r)[12]), "=r"((r)[13]), "=r"((r)[14]), "=r"((r)[15]), \
          "=r"((r)[16]), "=r"((r)[17]), "=r"((r)[18]), "=r"((r)[19]), \
          "=r"((r)[20]), "=r"((r)[21]), "=r"((r)[22]), "=r"((r)[23]), \
          "=r"((r)[24]), "=r"((r)[25]), "=r"((r)[26]), "=r"((r)[27]), \
          "=r"((r)[28]), "=r"((r)[29]), "=r"((r)[30]), "=r"((r)[31]) \
        : "r"(ta))
#define TCGEN05_LD_X16(r, ta) \
    asm volatile( \
        "tcgen05.ld.sync.aligned.32x32b.x16.b32 " \
        "{%0, %1, %2, %3, %4, %5, %6, %7, " \
        " %8, %9, %10, %11, %12, %13, %14, %15}, [%16];" \
        : "=r"((r)[0]),  "=r"((r)[1]),  "=r"((r)[2]),  "=r"((r)[3]), \
          "=r"((r)[4]),  "=r"((r)[5]),  "=r"((r)[6]),  "=r"((r)[7]), \
          "=r"((r)[8]),  "=r"((r)[9]),  "=r"((r)[10]), "=r"((r)[11]), \
          "=r"((r)[12]), "=r"((r)[13]), "=r"((r)[14]), "=r"((r)[15]) \
        : "r"(ta))
#define TCGEN05_LD_X8(r, ta) \
    asm volatile( \
        "tcgen05.ld.sync.aligned.32x32b.x8.b32 " \
        "{%0, %1, %2, %3, %4, %5, %6, %7}, [%8];" \
        : "=r"((r)[0]), "=r"((r)[1]), "=r"((r)[2]), "=r"((r)[3]), \
          "=r"((r)[4]), "=r"((r)[5]), "=r"((r)[6]), "=r"((r)[7]) \
        : "r"(ta))

// SS-mode cg1 bf16 MMA: D(TMEM) += A(smem desc) * B(smem desc)^T
__device__ __forceinline__ void mma_f16_ss(uint32_t d_tmem, uint64_t a_desc,
                                           uint64_t b_desc, uint32_t idesc,
                                           uint32_t en) {
    asm volatile(
        "{\n\t.reg .pred p;\n\t"
        "setp.ne.u32 p, %4, 0;\n\t"
        "tcgen05.mma.cta_group::1.kind::f16 [%0], %1, %2, %3, {%5, %5, %5, %5}, p;\n\t}"
        :: "r"(d_tmem), "l"(a_desc), "l"(b_desc), "r"(idesc), "r"(en), "r"(0u)
        : "memory");
}
#endif  // HAS_TCGEN05

static constexpr uint64_t SMEM_DESC_BASE_SW128 =
    (uint64_t(2) << 61) | (uint64_t(1) << 46) | (uint64_t(64) << 32) | (uint64_t(1) << 16);
#define MAKE_SMEM_DESC(a) (SMEM_DESC_BASE_SW128 | ((uint64_t)((a) >> 4) & 0x3FFF))
#define SWZ128(b) ((b) ^ (((b) >> 3) & 0x70))

// idesc: dtype F32(bit4) | atype BF16(bit7) | btype BF16(bit10) | N/8<<17 | M/16<<24
#define IDESC(NV) ((8u << 24) | (((NV) / 8u) << 17) | 0x490u)

// ---------------- graph prep ----------------
__global__ void k_zero_indeg() {
    int v = blockIdx.x * blockDim.x + threadIdx.x;
    if (v < NN) g_indeg[v] = 0;
}
__global__ void k_edge_prep(const int* __restrict__ ei) {
    int e = blockIdx.x * blockDim.x + threadIdx.x;
    if (e >= NE) return;
    int r = ei[e];
    int c = ei[NE + e];
    g_row[e] = r;
    g_col[e] = c;
    atomicAdd(&g_indeg[c], 1);
}
__global__ void k_dis() {
    int v = blockIdx.x * blockDim.x + threadIdx.x;
    if (v < NN) g_dis[v] = rsqrtf((float)(g_indeg[v] + 1));
}
__global__ void k_scan_local() {
    __shared__ int warp_sums[32];
    const int tid = threadIdx.x;
    const int v = blockIdx.x * 1024 + tid;
    int val = (v < NN) ? g_indeg[v] : 0;
    int x = val;
    #pragma unroll
    for (int o = 1; o < 32; o <<= 1) {
        int y = __shfl_up_sync(0xffffffffu, x, o);
        if ((tid & 31) >= o) x += y;
    }
    if ((tid & 31) == 31) warp_sums[tid >> 5] = x;
    __syncthreads();
    if (tid < 32) {
        int y = warp_sums[tid];
        #pragma unroll
        for (int o = 1; o < 32; o <<= 1) {
            int z = __shfl_up_sync(0xffffffffu, y, o);
            if (tid >= o) y += z;
        }
        warp_sums[tid] = y;
    }
    __syncthreads();
    int warp_prefix = (tid >= 32) ? warp_sums[(tid >> 5) - 1] : 0;
    if (v < NN) g_soff[v] = x + warp_prefix - val;
    if (tid == 0) g_bsum[blockIdx.x] = warp_sums[31];
}
__global__ void k_scan_bsum() {
    if (threadIdx.x == 0) {
        int run = 0;
        for (int b = 0; b < NB; b++) { int t = g_bsum[b]; g_bsum[b] = run; run += t; }
        g_soff[NN] = run;
    }
}
__global__ void k_scan_add() {
    int v = blockIdx.x * 1024 + threadIdx.x;
    if (v >= NN) return;
    int s = g_soff[v] + g_bsum[blockIdx.x];
    g_soff[v] = s;
    g_cursor[v] = s;
}
__global__ void k_scatter() {
    int e = blockIdx.x * blockDim.x + threadIdx.x;
    if (e >= NE) return;
    int r = g_row[e];
    int c = g_col[e];
    int pos = atomicAdd(&g_cursor[c], 1);
    float nrm = g_dis[r] * g_dis[c];
    g_sedge[pos] = make_uint2((unsigned)r, __float_as_uint(nrm));
}

// ---------------- weight prep: transpose + hi/lo split + atom-linearize ---
// B operand layout [Np rows(N), Kp cols(K)], atom = 8n x 64k (1024B):
// off = (n/8 + (k/64)*(Np/8))*512 + (n%8)*64 + (k%64)
__global__ void k_prep_w(const float* __restrict__ W, __nv_bfloat16* __restrict__ hi,
                         __nv_bfloat16* __restrict__ lo, int K, int N, int Kp, int Np) {
    int idx = blockIdx.x * blockDim.x + threadIdx.x;
    if (idx >= Kp * Np) return;
    int n = idx / Kp, k = idx % Kp;
    float v = (n < N && k < K) ? W[(size_t)k * N + n] : 0.f;
    __nv_bfloat16 h = __float2bfloat16(v);
    __nv_bfloat16 l = __float2bfloat16(v - __bfloat162float(h));
    int off = ((n >> 3) + (k >> 6) * (Np >> 3)) * 512 + (n & 7) * 64 + (k & 63);
    hi[off] = h;
    lo[off] = l;
}

// ---------------- CSR aggregation ----------------
template <int F>
__global__ void k_agg_csr(const float* __restrict__ src, float* __restrict__ dst) {
    int gtid = blockIdx.x * blockDim.x + threadIdx.x;
    int v    = gtid >> 5;
    int lane = gtid & 31;
    if (v >= NN) return;
    constexpr int NA = (F + 31) / 32;
    float acc[NA];
    float d = g_dis[v];
    const float* selfp = src + (size_t)v * F;
    #pragma unroll
    for (int i = 0; i < NA; i++) {
        int f = lane + 32 * i;
        acc[i] = (f < F) ? d * d * selfp[f] : 0.f;
    }
    int b  = g_soff[v];
    int e2 = g_soff[v + 1];
    for (int j = b; j < e2; j++) {
        uint2 pe = g_sedge[j];
        const float* sp = src + (size_t)pe.x * F;
        float w = __uint_as_float(pe.y);
        #pragma unroll
        for (int i = 0; i < NA; i++) {
            int f = lane + 32 * i;
            if (f < F) acc[i] += w * sp[f];
        }
    }
    float* dp = dst + (size_t)v * F;
    #pragma unroll
    for (int i = 0; i < NA; i++) {
        int f = lane + 32 * i;
        if (f < F) dp[f] = acc[i];
    }
}

// ================= Fused layer-1+2 tensor GEMM ============================
// Per CTA (128 rows):
//   D1 = agg1_tile @ W1 (TMEM cols 0..303)         [split-bf16, 3 products]
//   h1_tile = relu(D1 + b1), split hi/lo straight into smem (never to DRAM)
//   D2 = h1_tile @ W2 (TMEM cols 320..423), 5 K-chunks of 64
//   h2p_tile = D2 (staged through smem, coalesced store)
// smem (166912 B):
//   ctrl @0 | A2hi @1024 | A2lo @17408 | B2hi @33792 | B2lo @100352
//   phase-1 tiles aliased inside the B2 region (dead before B2 is filled):
//   A1hi @33792 | A1lo @50176 | B1hi @66560 | B1lo @105472
#define F_A2HI 1024
#define F_A2LO 17408
#define F_B2HI 33792
#define F_B2LO 100352
#define F_A1HI 33792
#define F_A1LO 50176
#define F_B1HI 66560
#define F_B1LO 105472
#define SMEMF  166912

__global__ void __launch_bounds__(256, 1)
k_tgemm12(const float* __restrict__ A, const float* __restrict__ b1,
          float* __restrict__ Cout) {
#if HAS_TCGEN05
    extern __shared__ char smem[];
    uint32_t sb = smem_to_u32(smem);
    int tid = threadIdx.x, wid = tid >> 5, lane = tid & 31;
    int brow = blockIdx.x * 128;

    if (wid == 0) { TCGEN05_ALLOC(sb + 0, 512); TCGEN05_RELINQ(); }
    if (tid == 0) MBARRIER_INIT(sb + 8, 1);
    __syncthreads();
    uint32_t tb = *(volatile uint32_t*)smem;
    const uint32_t tD1 = tb, tD2 = tb + 320;

    // ---- phase 1 fills ----
    // A1: [128 x 64 bf16] hi/lo from agg1 (fp32), SW128
    for (int i = tid; i < 128 * 64; i += 256) {
        int m = i >> 6, k = i & 63;
        int gm = brow + m;
        float v = (gm < NN && k < F0) ? A[(size_t)gm * F0 + k] : 0.f;
        __nv_bfloat16 h = __float2bfloat16(v);
        __nv_bfloat16 l = __float2bfloat16(v - __bfloat162float(h));
        uint32_t sw = SWZ128((uint32_t)((m << 7) + (k << 1)));
        *(__nv_bfloat16*)(smem + F_A1HI + sw) = h;
        *(__nv_bfloat16*)(smem + F_A1LO + sw) = l;
    }
    // B1: atom-linearized W1, 16B-granule swizzled copy
    for (int i = tid; i < (L1_NP * L1_KP) / 8; i += 256) {
        uint4 h = ((const uint4*)g_w1hi)[i];
        uint4 l = ((const uint4*)g_w1lo)[i];
        uint32_t sw = SWZ128((uint32_t)(i * 16));
        *(uint4*)(smem + F_B1HI + sw) = h;
        *(uint4*)(smem + F_B1LO + sw) = l;
    }
    FENCE_ASYNC();
    __syncthreads();

    // ---- MMA1: D1 = A1 @ W1^T (hi*hi + hi*lo + lo*hi) ----
    if (wid == 0 && elect_one_pred()) {
        uint64_t ah = MAKE_SMEM_DESC(sb + F_A1HI);
        uint64_t al = MAKE_SMEM_DESC(sb + F_A1LO);
        uint64_t bh = MAKE_SMEM_DESC(sb + F_B1HI);
        uint64_t bl = MAKE_SMEM_DESC(sb + F_B1LO);
        const uint32_t id0 = IDESC(256), id1 = IDESC(48);
        #pragma unroll
        for (int s = 0; s < 4; s++) {
            uint32_t en = (s > 0);
            mma_f16_ss(tD1,       ah + 2 * s, bh + 2 * s,        id0, en);
            mma_f16_ss(tD1 + 256, ah + 2 * s, bh + 2048 + 2 * s, id1, en);
            mma_f16_ss(tD1,       ah + 2 * s, bl + 2 * s,        id0, 1);
            mma_f16_ss(tD1 + 256, ah + 2 * s, bl + 2048 + 2 * s, id1, 1);
            mma_f16_ss(tD1,       al + 2 * s, bh + 2 * s,        id0, 1);
            mma_f16_ss(tD1 + 256, al + 2 * s, bh + 2048 + 2 * s, id1, 1);
        }
        TCGEN05_COMMIT(sb + 8);
    }
    mbar_wait(sb + 8, 0);
    TCGEN05_FENCE_AFTER();
    __syncthreads();      // A1/B1 dead from here

    // ---- B2 fill (overwrites phase-1 region) ----
    for (int i = tid; i < (L2_NP * L2_KP) / 8; i += 256) {
        uint4 h = ((const uint4*)g_w2hi)[i];
        uint4 l = ((const uint4*)g_w2lo)[i];
        uint32_t sw = SWZ128((uint32_t)(i * 16));
        *(uint4*)(smem + F_B2HI + sw) = h;
        *(uint4*)(smem + F_B2LO + sw) = l;
    }

    // ---- chunk loop: epilogue-split D1 -> A2 smem -> MMA2 chunk ----
    uint64_t a2h = MAKE_SMEM_DESC(sb + F_A2HI);
    uint64_t a2l = MAKE_SMEM_DESC(sb + F_A2LO);
    uint64_t b2h = MAKE_SMEM_DESC(sb + F_B2HI);
    uint64_t b2l = MAKE_SMEM_DESC(sb + F_B2LO);
    const uint32_t id2 = IDESC(104);

    for (int c = 0; c < 5; c++) {
        if (wid < 4) {
            int row = wid * 32 + lane;
            uint32_t r[64];
            if (c < 4) {
                TCGEN05_LD_X32(r,      tD1 + 64 * c);
                TCGEN05_LD_X32(r + 32, tD1 + 64 * c + 32);
            } else {
                TCGEN05_LD_X32(r,      tD1 + 256);
                TCGEN05_LD_X16(r + 32, tD1 + 288);
            }
            TCGEN05_WAIT_LD();
            #pragma unroll
            for (int j = 0; j < 64; j += 2) {
                int gc = 64 * c + j;
                float v0 = (gc     < F1) ? fmaxf(__uint_as_float(r[j])     + b1[gc],     0.f) : 0.f;
                float v1 = (gc + 1 < F1) ? fmaxf(__uint_as_float(r[j + 1]) + b1[gc + 1], 0.f) : 0.f;
                __nv_bfloat16 h0 = __float2bfloat16(v0);
                __nv_bfloat16 h1b = __float2bfloat16(v1);
                __nv_bfloat16 l0 = __float2bfloat16(v0 - __bfloat162float(h0));
                __nv_bfloat16 l1 = __float2bfloat16(v1 - __bfloat162float(h1b));
                __nv_bfloat162 ph = __halves2bfloat162(h0, h1b);
                __nv_bfloat162 pl = __halves2bfloat162(l0, l1);
                uint32_t sw = SWZ128((uint32_t)((row << 7) + (j << 1)));
                *(uint32_t*)(smem + F_A2HI + sw) = *(uint32_t*)&ph;
                *(uint32_t*)(smem + F_A2LO + sw) = *(uint32_t*)&pl;
            }
        }
        FENCE_ASYNC();
        __syncthreads();   // A2 ready; also covers B2 fill before chunk 0

        if (wid == 0 && elect_one_pred()) {
            uint32_t boff = c * 832;   // atom-col stride: 13 atoms * 1024B / 16
            #pragma unroll
            for (int s = 0; s < 4; s++) {
                uint32_t aoff = 2 * s, ko = boff + 2 * s;
                mma_f16_ss(tD2, a2h + aoff, b2h + ko, id2, (c > 0 || s > 0) ? 1u : 0u);
                mma_f16_ss(tD2, a2h + aoff, b2l + ko, id2, 1);
                mma_f16_ss(tD2, a2l + aoff, b2h + ko, id2, 1);
            }
            TCGEN05_COMMIT(sb + 8);
        }
        mbar_wait(sb + 8, (uint32_t)((c + 1) & 1));
        __syncthreads();   // A2 free for next chunk's epilogue writes
    }
    TCGEN05_FENCE_AFTER();

    // ---- final epilogue: D2 -> h2p (staged for coalescing) ----
    float* stg = (float*)(smem + 1024);   // 128 x 105 fp32 (A2 region, now dead)
    if (wid < 4) {
        int row = wid * 32 + lane;
        uint32_t r[32];
        #pragma unroll
        for (int g = 0; g < 3; g++) {
            TCGEN05_LD_X32(r, tD2 + g * 32);
            TCGEN05_WAIT_LD();
            for (int j = 0; j < 32; j++)
                stg[row * 105 + g * 32 + j] = __uint_as_float(r[j]);
        }
        TCGEN05_LD_X8(r, tD2 + 96);
        TCGEN05_WAIT_LD();
        for (int j = 0; j < 4; j++)
            stg[row * 105 + 96 + j] = __uint_as_float(r[j]);
    }
    __syncthreads();
    for (int i = tid; i < 128 * 100; i += 256) {
        int m = i / 100, cc = i - m * 100;
        int gm = brow + m;
        if (gm < NN) Cout[(size_t)gm * 100 + cc] = stg[m * 105 + cc];
    }
    __syncthreads();
    if (tid == 0) MBARRIER_INVAL(sb + 8);
    __syncthreads();
    if (wid == 0) TCGEN05_DEALLOC(tb, 512);
#endif
}

// ---------------- layer-3 fused dot + output ------------------------------
__global__ void k_dot3(const float* __restrict__ b2, const float* __restrict__ W3) {
    int gtid = blockIdx.x * blockDim.x + threadIdx.x;
    int v    = gtid >> 5;
    int lane = gtid & 31;
    if (v >= NN) return;
    const float* a = g_agg2 + (size_t)v * F2;
    float s = 0.f;
    for (int f = lane; f < F2; f += 32)
        s += fmaxf(a[f] + b2[f], 0.f) * W3[f];
    #pragma unroll
    for (int o = 16; o > 0; o >>= 1)
        s += __shfl_xor_sync(0xffffffffu, s, o);
    if (lane == 0) g_h3p[v] = s;
}
__global__ void k_out_csr(float* __restrict__ out, const float* __restrict__ b3) {
    int v = blockIdx.x * blockDim.x + threadIdx.x;
    if (v >= NN) return;
    float d = g_dis[v];
    float s = d * d * g_h3p[v];
    int b  = g_soff[v];
    int e2 = g_soff[v + 1];
    for (int j = b; j < e2; j++) {
        uint2 pe = g_sedge[j];
        s += __uint_as_float(pe.y) * g_h3p[pe.x];
    }
    out[v] = s + b3[0];
}

// ---------------- launch ----------------
extern "C" void kernel_launch(void* const* d_in, const int* in_sizes, int n_in,
                              void* d_out, int out_size) {
    const float* x  = (const float*)d_in[0];
    const int*   ei = (const int*)d_in[1];
    const float* W1 = (const float*)d_in[2];
    const float* b1 = (const float*)d_in[3];
    const float* W2 = (const float*)d_in[4];
    const float* b2 = (const float*)d_in[5];
    const float* W3 = (const float*)d_in[6];
    const float* b3 = (const float*)d_in[7];
    float* out = (float*)d_out;

    const int T = 256;
    float* agg1 = nullptr; cudaGetSymbolAddress((void**)&agg1, g_agg1);
    float* h2p  = nullptr; cudaGetSymbolAddress((void**)&h2p,  g_h2p);
    float* agg2 = nullptr; cudaGetSymbolAddress((void**)&agg2, g_agg2);
    __nv_bfloat16 *w1h, *w1l, *w2h, *w2l;
    cudaGetSymbolAddress((void**)&w1h, g_w1hi);
    cudaGetSymbolAddress((void**)&w1l, g_w1lo);
    cudaGetSymbolAddress((void**)&w2h, g_w2hi);
    cudaGetSymbolAddress((void**)&w2l, g_w2lo);

    cudaFuncSetAttribute(k_tgemm12, cudaFuncAttributeMaxDynamicSharedMemorySize, SMEMF);

    // weight prep (graph-independent)
    k_prep_w<<<(L1_NP * L1_KP + T - 1) / T, T>>>(W1, w1h, w1l, F0, F1, L1_KP, L1_NP);
    k_prep_w<<<(L2_NP * L2_KP + T - 1) / T, T>>>(W2, w2h, w2l, F1, F2, L2_KP, L2_NP);

    // CSR build
    k_zero_indeg<<<(NN + T - 1) / T, T>>>();
    k_edge_prep<<<(NE + T - 1) / T, T>>>(ei);
    k_dis<<<(NN + T - 1) / T, T>>>();
    k_scan_local<<<NB, 1024>>>();
    k_scan_bsum<<<1, 32>>>();
    k_scan_add<<<NB, 1024>>>();
    k_scatter<<<(NE + T - 1) / T, T>>>();

    const unsigned aggGrid = (unsigned)(((long long)NN * 32 + T - 1) / T);

    // Layers 1+2 fused: aggregate(58) -> [GEMM1 + bias/relu + GEMM2] -> h2p
    k_agg_csr<F0><<<aggGrid, T>>>(x, agg1);
    k_tgemm12<<<MTILES, 256, SMEMF>>>(agg1, b1, h2p);
    k_agg_csr<F2><<<aggGrid, T>>>(h2p, agg2);

    // Layer 3
    k_dot3<<<aggGrid, T>>>(b2, W3);
    k_out_csr<<<(NN + T - 1) / T, T>>>(out, b3);

    (void)in_sizes; (void)n_in; (void)out_size;
}

// round 10
// speedup vs baseline: 2.3786x; 1.1097x over previous
#include <cuda_runtime.h>
#include <cuda_bf16.h>
#include <math.h>
#include <stdint.h>

// tcgen05 is only legal on arch-specific targets (sm_103a). The harness also
// runs a plain compute_103 PTX pass; gate the tensor kernels so that pass
// compiles a stub (never executed — exact sm_103a cubin always wins).
#if defined(__CUDA_ARCH_FEAT_SM103_ALL) || defined(__CUDA_ARCH_SPECIFIC__) || defined(__CUDA_ARCH_FAMILY_SPECIFIC__)
#define HAS_TCGEN05 1
#else
#define HAS_TCGEN05 0
#endif

#define NN 100000      // nodes
#define NE 1000000     // edges
#define F0 58
#define F1 300
#define F2 100
#define NB 98          // ceil(NN / 1024) scan blocks
#define MTILES 782     // ceil(NN / 128)

// tensor-layer padded dims
#define L1_KP 64       // K: 58 -> 64
#define L1_NP 304      // N: 300 -> 304
#define L2_KP 320      // K: 300 -> 320
#define L2_NP 104      // N: 100 -> 104

// ---------------- device scratch (allocation-free rule: static globals) ----
__device__ int      g_indeg[NN];
__device__ float    g_dis[NN];
__device__ int      g_row[NE];
__device__ int      g_col[NE];
__device__ int      g_soff[NN + 1];
__device__ int      g_cursor[NN];
__device__ int      g_bsum[NB];
__device__ uint2    g_sedge[NE];
__device__ float    g_agg1[(size_t)NN * F0];
__device__ float    g_h2p [(size_t)NN * F2];
__device__ float    g_h3p [NN];
__device__ __nv_bfloat16 g_w1hi[L1_NP * L1_KP];  // atom-linearized W1^T
__device__ __nv_bfloat16 g_w1lo[L1_NP * L1_KP];
__device__ __nv_bfloat16 g_w2hi[L2_NP * L2_KP];
__device__ __nv_bfloat16 g_w2lo[L2_NP * L2_KP];

// ---------------- PTX helpers ----------------
__device__ __forceinline__ uint32_t smem_to_u32(const void* p) {
    uint32_t a;
    asm("{ .reg .u64 t; cvta.to.shared.u64 t, %1; cvt.u32.u64 %0, t; }"
        : "=r"(a) : "l"(p));
    return a;
}

#if HAS_TCGEN05
__device__ __forceinline__ uint32_t elect_one_pred() {
    uint32_t pred;
    asm volatile(
        "{\n\t.reg .pred p;\n\t"
        "elect.sync _|p, 0xFFFFFFFF;\n\t"
        "selp.b32 %0, 1, 0, p;\n\t}"
        : "=r"(pred));
    return pred;
}
#define TCGEN05_ALLOC(saddr, n) \
    asm volatile("tcgen05.alloc.cta_group::1.sync.aligned.shared::cta.b32 [%0], %1;" \
                 :: "r"((uint32_t)(saddr)), "r"((uint32_t)(n)) : "memory")
#define TCGEN05_RELINQ() \
    asm volatile("tcgen05.relinquish_alloc_permit.cta_group::1.sync.aligned;")
#define TCGEN05_DEALLOC(t, n) \
    asm volatile("tcgen05.dealloc.cta_group::1.sync.aligned.b32 %0, %1;" :: "r"(t), "r"((uint32_t)(n)))
#define TCGEN05_COMMIT(mbar) \
    asm volatile("tcgen05.commit.cta_group::1.mbarrier::arrive::one.shared::cluster.b64 [%0];" \
                 :: "r"((uint32_t)(mbar)) : "memory")
#define TCGEN05_FENCE_AFTER() asm volatile("tcgen05.fence::after_thread_sync;" ::: "memory")
#define TCGEN05_WAIT_LD()     asm volatile("tcgen05.wait::ld.sync.aligned;" ::: "memory")
#define FENCE_ASYNC()         asm volatile("fence.proxy.async.shared::cta;" ::: "memory")
#define MBARRIER_INIT(mbar, cnt) \
    asm volatile("mbarrier.init.shared.b64 [%0], %1;" :: "r"((uint32_t)(mbar)), "r"((uint32_t)(cnt)) : "memory")
#define MBARRIER_INVAL(mbar) \
    asm volatile("mbarrier.inval.shared.b64 [%0];" :: "r"((uint32_t)(mbar)) : "memory")

__device__ __forceinline__ void mbar_wait(uint32_t mbar, uint32_t parity) {
    uint32_t done;
    asm volatile(
        "{\n\t.reg .pred p;\n\t"
        "mbarrier.try_wait.parity.acquire.cta.shared::cta.b64 p, [%1], %2;\n\t"
        "selp.b32 %0, 1, 0, p;\n\t}"
        : "=r"(done) : "r"(mbar), "r"(parity) : "memory");
    if (!done) {
        asm volatile(
            "{\n\t.reg .pred P1;\n\t"
            "WAIT_LOOP_%=:\n\t"
            "mbarrier.try_wait.parity.acquire.cta.shared::cta.b64 P1, [%0], %1, 0x989680;\n\t"
            "@P1 bra.uni WAIT_DONE_%=;\n\t"
            "bra.uni WAIT_LOOP_%=;\n\t"
            "WAIT_DONE_%=:\n\t}"
            :: "r"(mbar), "r"(parity) : "memory");
    }
}

#define TCGEN05_LD_X32(r, ta) \
    asm volatile( \
        "tcgen05.ld.sync.aligned.32x32b.x32.b32 " \
        "{%0, %1, %2, %3, %4, %5, %6, %7, " \
        " %8, %9, %10, %11, %12, %13, %14, %15, " \
        " %16, %17, %18, %19, %20, %21, %22, %23, " \
        " %24, %25, %26, %27, %28, %29, %30, %31}, [%32];" \
        : "=r"((r)[0]),  "=r"((r)[1]),  "=r"((r)[2]),  "=r"((r)[3]), \
          "=r"((r)[4]),  "=r"((r)[5]),  "=r"((r)[6]),  "=r"((r)[7]), \
          "=r"((r)[8]),  "=r"((r)[9]),  "=r"((r)[10]), "=r"((r)[11]), \
          "=r"((r)[12]), "=r"((r)[13]), "=r"((r)[14]), "=r"((r)[15]), \
          "=r"((r)[16]), "=r"((r)[17]), "=r"((r)[18]), "=r"((r)[19]), \
          "=r"((r)[20]), "=r"((r)[21]), "=r"((r)[22]), "=r"((r)[23]), \
          "=r"((r)[24]), "=r"((r)[25]), "=r"((r)[26]), "=r"((r)[27]), \
          "=r"((r)[28]), "=r"((r)[29]), "=r"((r)[30]), "=r"((r)[31]) \
        : "r"(ta))
#define TCGEN05_LD_X16(r, ta) \
    asm volatile( \
        "tcgen05.ld.sync.aligned.32x32b.x16.b32 " \
        "{%0, %1, %2, %3, %4, %5, %6, %7, " \
        " %8, %9, %10, %11, %12, %13, %14, %15}, [%16];" \
        : "=r"((r)[0]),  "=r"((r)[1]),  "=r"((r)[2]),  "=r"((r)[3]), \
          "=r"((r)[4]),  "=r"((r)[5]),  "=r"((r)[6]),  "=r"((r)[7]), \
          "=r"((r)[8]),  "=r"((r)[9]),  "=r"((r)[10]), "=r"((r)[11]), \
          "=r"((r)[12]), "=r"((r)[13]), "=r"((r)[14]), "=r"((r)[15]) \
        : "r"(ta))
#define TCGEN05_LD_X8(r, ta) \
    asm volatile( \
        "tcgen05.ld.sync.aligned.32x32b.x8.b32 " \
        "{%0, %1, %2, %3, %4, %5, %6, %7}, [%8];" \
        : "=r"((r)[0]), "=r"((r)[1]), "=r"((r)[2]), "=r"((r)[3]), \
          "=r"((r)[4]), "=r"((r)[5]), "=r"((r)[6]), "=r"((r)[7]) \
        : "r"(ta))

// SS-mode cg1 bf16 MMA: D(TMEM) += A(smem desc) * B(smem desc)^T
__device__ __forceinline__ void mma_f16_ss(uint32_t d_tmem, uint64_t a_desc,
                                           uint64_t b_desc, uint32_t idesc,
                                           uint32_t en) {
    asm volatile(
        "{\n\t.reg .pred p;\n\t"
        "setp.ne.u32 p, %4, 0;\n\t"
        "tcgen05.mma.cta_group::1.kind::f16 [%0], %1, %2, %3, {%5, %5, %5, %5}, p;\n\t}"
        :: "r"(d_tmem), "l"(a_desc), "l"(b_desc), "r"(idesc), "r"(en), "r"(0u)
        : "memory");
}
#endif  // HAS_TCGEN05

static constexpr uint64_t SMEM_DESC_BASE_SW128 =
    (uint64_t(2) << 61) | (uint64_t(1) << 46) | (uint64_t(64) << 32) | (uint64_t(1) << 16);
#define MAKE_SMEM_DESC(a) (SMEM_DESC_BASE_SW128 | ((uint64_t)((a) >> 4) & 0x3FFF))
#define SWZ128(b) ((b) ^ (((b) >> 3) & 0x70))

// idesc: dtype F32(bit4) | atype BF16(bit7) | btype BF16(bit10) | N/8<<17 | M/16<<24
#define IDESC(NV) ((8u << 24) | (((NV) / 8u) << 17) | 0x490u)

// ---------------- graph prep ----------------
__global__ void k_zero_indeg() {
    int v = blockIdx.x * blockDim.x + threadIdx.x;
    if (v < NN) g_indeg[v] = 0;
}
__global__ void k_edge_prep(const int* __restrict__ ei) {
    int e = blockIdx.x * blockDim.x + threadIdx.x;
    if (e >= NE) return;
    int r = ei[e];
    int c = ei[NE + e];
    g_row[e] = r;
    g_col[e] = c;
    atomicAdd(&g_indeg[c], 1);
}
// phase 1: local exclusive scan (1024/block) + block total; also emits dis
__global__ void k_scan_local() {
    __shared__ int warp_sums[32];
    const int tid = threadIdx.x;
    const int v = blockIdx.x * 1024 + tid;
    int val = (v < NN) ? g_indeg[v] : 0;
    if (v < NN) g_dis[v] = rsqrtf((float)(val + 1));   // +1 self-loop
    int x = val;
    #pragma unroll
    for (int o = 1; o < 32; o <<= 1) {
        int y = __shfl_up_sync(0xffffffffu, x, o);
        if ((tid & 31) >= o) x += y;
    }
    if ((tid & 31) == 31) warp_sums[tid >> 5] = x;
    __syncthreads();
    if (tid < 32) {
        int y = warp_sums[tid];
        #pragma unroll
        for (int o = 1; o < 32; o <<= 1) {
            int z = __shfl_up_sync(0xffffffffu, y, o);
            if (tid >= o) y += z;
        }
        warp_sums[tid] = y;
    }
    __syncthreads();
    int warp_prefix = (tid >= 32) ? warp_sums[(tid >> 5) - 1] : 0;
    if (v < NN) g_soff[v] = x + warp_prefix - val;
    if (tid == 0) g_bsum[blockIdx.x] = warp_sums[31];
}
__global__ void k_scan_bsum() {
    if (threadIdx.x == 0) {
        int run = 0;
        for (int b = 0; b < NB; b++) { int t = g_bsum[b]; g_bsum[b] = run; run += t; }
        g_soff[NN] = run;
    }
}
__global__ void k_scan_add() {
    int v = blockIdx.x * 1024 + threadIdx.x;
    if (v >= NN) return;
    int s = g_soff[v] + g_bsum[blockIdx.x];
    g_soff[v] = s;
    g_cursor[v] = s;
}
__global__ void k_scatter() {
    int e = blockIdx.x * blockDim.x + threadIdx.x;
    if (e >= NE) return;
    int r = g_row[e];
    int c = g_col[e];
    int pos = atomicAdd(&g_cursor[c], 1);
    float nrm = g_dis[r] * g_dis[c];
    g_sedge[pos] = make_uint2((unsigned)r, __float_as_uint(nrm));
}

// ---------------- weight prep: transpose + hi/lo split + atom-linearize ---
// B operand layout [Np rows(N), Kp cols(K)], atom = 8n x 64k (1024B):
// off = (n/8 + (k/64)*(Np/8))*512 + (n%8)*64 + (k%64)
__global__ void k_prep_w(const float* __restrict__ W, __nv_bfloat16* __restrict__ hi,
                         __nv_bfloat16* __restrict__ lo, int K, int N, int Kp, int Np) {
    int idx = blockIdx.x * blockDim.x + threadIdx.x;
    if (idx >= Kp * Np) return;
    int n = idx / Kp, k = idx % Kp;
    float v = (n < N && k < K) ? W[(size_t)k * N + n] : 0.f;
    __nv_bfloat16 h = __float2bfloat16(v);
    __nv_bfloat16 l = __float2bfloat16(v - __bfloat162float(h));
    int off = ((n >> 3) + (k >> 6) * (Np >> 3)) * 512 + (n & 7) * 64 + (k & 63);
    hi[off] = h;
    lo[off] = l;
}

// ---------------- CSR aggregation (layer 1): agg1 = D^-1/2 A D^-1/2 x ------
template <int F>
__global__ void k_agg_csr(const float* __restrict__ src, float* __restrict__ dst) {
    int gtid = blockIdx.x * blockDim.x + threadIdx.x;
    int v    = gtid >> 5;
    int lane = gtid & 31;
    if (v >= NN) return;
    constexpr int NA = (F + 31) / 32;
    float acc[NA];
    float d = g_dis[v];
    const float* selfp = src + (size_t)v * F;
    #pragma unroll
    for (int i = 0; i < NA; i++) {
        int f = lane + 32 * i;
        acc[i] = (f < F) ? d * d * selfp[f] : 0.f;
    }
    int b  = g_soff[v];
    int e2 = g_soff[v + 1];
    int j = b;
    for (; j + 1 < e2; j += 2) {           // 2-edge unroll: 2x MLP
        uint2 p0 = g_sedge[j];
        uint2 p1 = g_sedge[j + 1];
        const float* s0 = src + (size_t)p0.x * F;
        const float* s1 = src + (size_t)p1.x * F;
        float w0 = __uint_as_float(p0.y);
        float w1 = __uint_as_float(p1.y);
        #pragma unroll
        for (int i = 0; i < NA; i++) {
            int f = lane + 32 * i;
            if (f < F) {
                float a0 = s0[f], a1 = s1[f];
                acc[i] += w0 * a0;
                acc[i] += w1 * a1;
            }
        }
    }
    if (j < e2) {
        uint2 pe = g_sedge[j];
        const float* sp = src + (size_t)pe.x * F;
        float w = __uint_as_float(pe.y);
        #pragma unroll
        for (int i = 0; i < NA; i++) {
            int f = lane + 32 * i;
            if (f < F) acc[i] += w * sp[f];
        }
    }
    float* dp = dst + (size_t)v * F;
    #pragma unroll
    for (int i = 0; i < NA; i++) {
        int f = lane + 32 * i;
        if (f < F) dp[f] = acc[i];
    }
}

// ---- layer-2 aggregation fused with layer-3 dot:
// h3p[v] = sum_f relu(agg2[v,f] + b2[f]) * W3[f]  (agg2 never materialized)
__global__ void k_agg2dot(const float* __restrict__ src,
                          const float* __restrict__ b2,
                          const float* __restrict__ W3) {
    int gtid = blockIdx.x * blockDim.x + threadIdx.x;
    int v    = gtid >> 5;
    int lane = gtid & 31;
    if (v >= NN) return;
    constexpr int F = F2, NA = 4;
    float acc[NA];
    float d = g_dis[v];
    const float* selfp = src + (size_t)v * F;
    #pragma unroll
    for (int i = 0; i < NA; i++) {
        int f = lane + 32 * i;
        acc[i] = (f < F) ? d * d * selfp[f] : 0.f;
    }
    int b  = g_soff[v];
    int e2 = g_soff[v + 1];
    int j = b;
    for (; j + 1 < e2; j += 2) {
        uint2 p0 = g_sedge[j];
        uint2 p1 = g_sedge[j + 1];
        const float* s0 = src + (size_t)p0.x * F;
        const float* s1 = src + (size_t)p1.x * F;
        float w0 = __uint_as_float(p0.y);
        float w1 = __uint_as_float(p1.y);
        #pragma unroll
        for (int i = 0; i < NA; i++) {
            int f = lane + 32 * i;
            if (f < F) {
                float a0 = s0[f], a1 = s1[f];
                acc[i] += w0 * a0;
                acc[i] += w1 * a1;
            }
        }
    }
    if (j < e2) {
        uint2 pe = g_sedge[j];
        const float* sp = src + (size_t)pe.x * F;
        float w = __uint_as_float(pe.y);
        #pragma unroll
        for (int i = 0; i < NA; i++) {
            int f = lane + 32 * i;
            if (f < F) acc[i] += w * sp[f];
        }
    }
    // fused bias + relu + dot(W3) + warp reduce
    float s = 0.f;
    #pragma unroll
    for (int i = 0; i < NA; i++) {
        int f = lane + 32 * i;
        if (f < F) s += fmaxf(acc[i] + b2[f], 0.f) * W3[f];
    }
    #pragma unroll
    for (int o = 16; o > 0; o >>= 1)
        s += __shfl_xor_sync(0xffffffffu, s, o);
    if (lane == 0) g_h3p[v] = s;
}

// ================= Fused layer-1+2 tensor GEMM ============================
// Per CTA (128 rows):
//   D1 = agg1_tile @ W1 (TMEM cols 0..303)         [split-bf16, 3 products]
//   h1_tile = relu(D1 + b1), split hi/lo straight into smem (never to DRAM)
//   D2 = h1_tile @ W2 (TMEM cols 320..423), 5 K-chunks of 64
//   h2p_tile = D2 (staged through smem, coalesced store)
#define F_A2HI 1024
#define F_A2LO 17408
#define F_B2HI 33792
#define F_B2LO 100352
#define F_A1HI 33792
#define F_A1LO 50176
#define F_B1HI 66560
#define F_B1LO 105472
#define SMEMF  166912

__global__ void __launch_bounds__(256, 1)
k_tgemm12(const float* __restrict__ A, const float* __restrict__ b1,
          float* __restrict__ Cout) {
#if HAS_TCGEN05
    extern __shared__ char smem[];
    uint32_t sb = smem_to_u32(smem);
    int tid = threadIdx.x, wid = tid >> 5, lane = tid & 31;
    int brow = blockIdx.x * 128;

    if (wid == 0) { TCGEN05_ALLOC(sb + 0, 512); TCGEN05_RELINQ(); }
    if (tid == 0) MBARRIER_INIT(sb + 8, 1);
    __syncthreads();
    uint32_t tb = *(volatile uint32_t*)smem;
    const uint32_t tD1 = tb, tD2 = tb + 320;

    // ---- phase 1 fills ----
    for (int i = tid; i < 128 * 64; i += 256) {
        int m = i >> 6, k = i & 63;
        int gm = brow + m;
        float v = (gm < NN && k < F0) ? A[(size_t)gm * F0 + k] : 0.f;
        __nv_bfloat16 h = __float2bfloat16(v);
        __nv_bfloat16 l = __float2bfloat16(v - __bfloat162float(h));
        uint32_t sw = SWZ128((uint32_t)((m << 7) + (k << 1)));
        *(__nv_bfloat16*)(smem + F_A1HI + sw) = h;
        *(__nv_bfloat16*)(smem + F_A1LO + sw) = l;
    }
    for (int i = tid; i < (L1_NP * L1_KP) / 8; i += 256) {
        uint4 h = ((const uint4*)g_w1hi)[i];
        uint4 l = ((const uint4*)g_w1lo)[i];
        uint32_t sw = SWZ128((uint32_t)(i * 16));
        *(uint4*)(smem + F_B1HI + sw) = h;
        *(uint4*)(smem + F_B1LO + sw) = l;
    }
    FENCE_ASYNC();
    __syncthreads();

    // ---- MMA1: D1 = A1 @ W1^T (hi*hi + hi*lo + lo*hi) ----
    if (wid == 0 && elect_one_pred()) {
        uint64_t ah = MAKE_SMEM_DESC(sb + F_A1HI);
        uint64_t al = MAKE_SMEM_DESC(sb + F_A1LO);
        uint64_t bh = MAKE_SMEM_DESC(sb + F_B1HI);
        uint64_t bl = MAKE_SMEM_DESC(sb + F_B1LO);
        const uint32_t id0 = IDESC(256), id1 = IDESC(48);
        #pragma unroll
        for (int s = 0; s < 4; s++) {
            uint32_t en = (s > 0);
            mma_f16_ss(tD1,       ah + 2 * s, bh + 2 * s,        id0, en);
            mma_f16_ss(tD1 + 256, ah + 2 * s, bh + 2048 + 2 * s, id1, en);
            mma_f16_ss(tD1,       ah + 2 * s, bl + 2 * s,        id0, 1);
            mma_f16_ss(tD1 + 256, ah + 2 * s, bl + 2048 + 2 * s, id1, 1);
            mma_f16_ss(tD1,       al + 2 * s, bh + 2 * s,        id0, 1);
            mma_f16_ss(tD1 + 256, al + 2 * s, bh + 2048 + 2 * s, id1, 1);
        }
        TCGEN05_COMMIT(sb + 8);
    }
    mbar_wait(sb + 8, 0);
    TCGEN05_FENCE_AFTER();
    __syncthreads();      // A1/B1 dead from here

    // ---- B2 fill (overwrites phase-1 region) ----
    for (int i = tid; i < (L2_NP * L2_KP) / 8; i += 256) {
        uint4 h = ((const uint4*)g_w2hi)[i];
        uint4 l = ((const uint4*)g_w2lo)[i];
        uint32_t sw = SWZ128((uint32_t)(i * 16));
        *(uint4*)(smem + F_B2HI + sw) = h;
        *(uint4*)(smem + F_B2LO + sw) = l;
    }

    // ---- chunk loop: epilogue-split D1 -> A2 smem -> MMA2 chunk ----
    uint64_t a2h = MAKE_SMEM_DESC(sb + F_A2HI);
    uint64_t a2l = MAKE_SMEM_DESC(sb + F_A2LO);
    uint64_t b2h = MAKE_SMEM_DESC(sb + F_B2HI);
    uint64_t b2l = MAKE_SMEM_DESC(sb + F_B2LO);
    const uint32_t id2 = IDESC(104);

    for (int c = 0; c < 5; c++) {
        if (wid < 4) {
            int row = wid * 32 + lane;
            uint32_t r[64];
            if (c < 4) {
                TCGEN05_LD_X32(r,      tD1 + 64 * c);
                TCGEN05_LD_X32(r + 32, tD1 + 64 * c + 32);
            } else {
                TCGEN05_LD_X32(r,      tD1 + 256);
                TCGEN05_LD_X16(r + 32, tD1 + 288);
            }
            TCGEN05_WAIT_LD();
            #pragma unroll
            for (int j = 0; j < 64; j += 2) {
                int gc = 64 * c + j;
                float v0 = (gc     < F1) ? fmaxf(__uint_as_float(r[j])     + b1[gc],     0.f) : 0.f;
                float v1 = (gc + 1 < F1) ? fmaxf(__uint_as_float(r[j + 1]) + b1[gc + 1], 0.f) : 0.f;
                __nv_bfloat16 h0 = __float2bfloat16(v0);
                __nv_bfloat16 h1b = __float2bfloat16(v1);
                __nv_bfloat16 l0 = __float2bfloat16(v0 - __bfloat162float(h0));
                __nv_bfloat16 l1 = __float2bfloat16(v1 - __bfloat162float(h1b));
                __nv_bfloat162 ph = __halves2bfloat162(h0, h1b);
                __nv_bfloat162 pl = __halves2bfloat162(l0, l1);
                uint32_t sw = SWZ128((uint32_t)((row << 7) + (j << 1)));
                *(uint32_t*)(smem + F_A2HI + sw) = *(uint32_t*)&ph;
                *(uint32_t*)(smem + F_A2LO + sw) = *(uint32_t*)&pl;
            }
        }
        FENCE_ASYNC();
        __syncthreads();   // A2 ready; also covers B2 fill before chunk 0

        if (wid == 0 && elect_one_pred()) {
            uint32_t boff = c * 832;   // atom-col stride: 13 atoms * 1024B / 16
            #pragma unroll
            for (int s = 0; s < 4; s++) {
                uint32_t aoff = 2 * s, ko = boff + 2 * s;
                mma_f16_ss(tD2, a2h + aoff, b2h + ko, id2, (c > 0 || s > 0) ? 1u : 0u);
                mma_f16_ss(tD2, a2h + aoff, b2l + ko, id2, 1);
                mma_f16_ss(tD2, a2l + aoff, b2h + ko, id2, 1);
            }
            TCGEN05_COMMIT(sb + 8);
        }
        mbar_wait(sb + 8, (uint32_t)((c + 1) & 1));
        __syncthreads();   // A2 free for next chunk's epilogue writes
    }
    TCGEN05_FENCE_AFTER();

    // ---- final epilogue: D2 -> h2p (staged for coalescing) ----
    float* stg = (float*)(smem + 1024);   // 128 x 105 fp32 (A2 region, now dead)
    if (wid < 4) {
        int row = wid * 32 + lane;
        uint32_t r[32];
        #pragma unroll
        for (int g = 0; g < 3; g++) {
            TCGEN05_LD_X32(r, tD2 + g * 32);
            TCGEN05_WAIT_LD();
            for (int j = 0; j < 32; j++)
                stg[row * 105 + g * 32 + j] = __uint_as_float(r[j]);
        }
        TCGEN05_LD_X8(r, tD2 + 96);
        TCGEN05_WAIT_LD();
        for (int j = 0; j < 4; j++)
            stg[row * 105 + 96 + j] = __uint_as_float(r[j]);
    }
    __syncthreads();
    for (int i = tid; i < 128 * 100; i += 256) {
        int m = i / 100, cc = i - m * 100;
        int gm = brow + m;
        if (gm < NN) Cout[(size_t)gm * 100 + cc] = stg[m * 105 + cc];
    }
    __syncthreads();
    if (tid == 0) MBARRIER_INVAL(sb + 8);
    __syncthreads();
    if (wid == 0) TCGEN05_DEALLOC(tb, 512);
#endif
}

// ---------------- final output: CSR aggregate of h3p ----------------------
__global__ void k_out_csr(float* __restrict__ out, const float* __restrict__ b3) {
    int v = blockIdx.x * blockDim.x + threadIdx.x;
    if (v >= NN) return;
    float d = g_dis[v];
    float s = d * d * g_h3p[v];
    int b  = g_soff[v];
    int e2 = g_soff[v + 1];
    for (int j = b; j < e2; j++) {
        uint2 pe = g_sedge[j];
        s += __uint_as_float(pe.y) * g_h3p[pe.x];
    }
    out[v] = s + b3[0];
}

// ---------------- launch ----------------
extern "C" void kernel_launch(void* const* d_in, const int* in_sizes, int n_in,
                              void* d_out, int out_size) {
    const float* x  = (const float*)d_in[0];
    const int*   ei = (const int*)d_in[1];
    const float* W1 = (const float*)d_in[2];
    const float* b1 = (const float*)d_in[3];
    const float* W2 = (const float*)d_in[4];
    const float* b2 = (const float*)d_in[5];
    const float* W3 = (const float*)d_in[6];
    const float* b3 = (const float*)d_in[7];
    float* out = (float*)d_out;

    const int T = 256;
    float* agg1 = nullptr; cudaGetSymbolAddress((void**)&agg1, g_agg1);
    float* h2p  = nullptr; cudaGetSymbolAddress((void**)&h2p,  g_h2p);
    __nv_bfloat16 *w1h, *w1l, *w2h, *w2l;
    cudaGetSymbolAddress((void**)&w1h, g_w1hi);
    cudaGetSymbolAddress((void**)&w1l, g_w1lo);
    cudaGetSymbolAddress((void**)&w2h, g_w2hi);
    cudaGetSymbolAddress((void**)&w2l, g_w2lo);

    cudaFuncSetAttribute(k_tgemm12, cudaFuncAttributeMaxDynamicSharedMemorySize, SMEMF);

    // weight prep (graph-independent)
    k_prep_w<<<(L1_NP * L1_KP + T - 1) / T, T>>>(W1, w1h, w1l, F0, F1, L1_KP, L1_NP);
    k_prep_w<<<(L2_NP * L2_KP + T - 1) / T, T>>>(W2, w2h, w2l, F1, F2, L2_KP, L2_NP);

    // CSR build (dis folded into scan_local)
    k_zero_indeg<<<(NN + T - 1) / T, T>>>();
    k_edge_prep<<<(NE + T - 1) / T, T>>>(ei);
    k_scan_local<<<NB, 1024>>>();
    k_scan_bsum<<<1, 32>>>();
    k_scan_add<<<NB, 1024>>>();
    k_scatter<<<(NE + T - 1) / T, T>>>();

    const unsigned aggGrid = (unsigned)(((long long)NN * 32 + T - 1) / T);

    // Layers 1+2 fused: aggregate(58) -> [GEMM1 + bias/relu + GEMM2] -> h2p
    k_agg_csr<F0><<<aggGrid, T>>>(x, agg1);
    k_tgemm12<<<MTILES, 256, SMEMF>>>(agg1, b1, h2p);

    // Layer-2 aggregation fused with layer-3 dot -> h3p, then final CSR out
    k_agg2dot<<<aggGrid, T>>>(h2p, b2, W3);
    k_out_csr<<<(NN + T - 1) / T, T>>>(out, b3);

    (void)in_sizes; (void)n_in; (void)out_size;
}

// round 11
// speedup vs baseline: 2.5670x; 1.0792x over previous
#include <cuda_runtime.h>
#include <cuda_bf16.h>
#include <math.h>
#include <stdint.h>

// tcgen05 is only legal on arch-specific targets (sm_103a). The harness also
// runs a plain compute_103 PTX pass; gate the tensor kernels so that pass
// compiles a stub (never executed — exact sm_103a cubin always wins).
#if defined(__CUDA_ARCH_FEAT_SM103_ALL) || defined(__CUDA_ARCH_SPECIFIC__) || defined(__CUDA_ARCH_FAMILY_SPECIFIC__)
#define HAS_TCGEN05 1
#else
#define HAS_TCGEN05 0
#endif

#define NN 100000      // nodes
#define NE 1000000     // edges
#define F0 58
#define F1 300
#define F2 100
#define NB 98          // ceil(NN / 1024) scan blocks
#define MTILES 782     // ceil(NN / 128)
#define H2W 52         // u32 words per h2 row (50 data + 2 pad, 16B-aligned stride)

// tensor-layer padded dims
#define L1_KP 64       // K: 58 -> 64
#define L1_NP 304      // N: 300 -> 304
#define L2_KP 320      // K: 300 -> 320
#define L2_NP 104      // N: 100 -> 104

// ---------------- device scratch (allocation-free rule: static globals) ----
__device__ int      g_indeg[NN];
__device__ float    g_dis[NN];
__device__ int      g_soff[NN + 1];
__device__ int      g_cursor[NN];
__device__ int      g_bsum[NB];
__device__ uint2    g_sedge[NE];
__device__ float    g_agg1[(size_t)NN * F0];
__device__ unsigned g_h2b [(size_t)NN * H2W];   // h2p as packed bf16x2
__device__ float    g_h3p [NN];
__device__ __nv_bfloat16 g_w1hi[L1_NP * L1_KP]; // atom-linearized W1^T
__device__ __nv_bfloat16 g_w1lo[L1_NP * L1_KP];
__device__ __nv_bfloat16 g_w2hi[L2_NP * L2_KP];
__device__ __nv_bfloat16 g_w2lo[L2_NP * L2_KP];

// ---------------- PTX helpers ----------------
__device__ __forceinline__ uint32_t smem_to_u32(const void* p) {
    uint32_t a;
    asm("{ .reg .u64 t; cvta.to.shared.u64 t, %1; cvt.u32.u64 %0, t; }"
        : "=r"(a) : "l"(p));
    return a;
}

#if HAS_TCGEN05
__device__ __forceinline__ uint32_t elect_one_pred() {
    uint32_t pred;
    asm volatile(
        "{\n\t.reg .pred p;\n\t"
        "elect.sync _|p, 0xFFFFFFFF;\n\t"
        "selp.b32 %0, 1, 0, p;\n\t}"
        : "=r"(pred));
    return pred;
}
#define TCGEN05_ALLOC(saddr, n) \
    asm volatile("tcgen05.alloc.cta_group::1.sync.aligned.shared::cta.b32 [%0], %1;" \
                 :: "r"((uint32_t)(saddr)), "r"((uint32_t)(n)) : "memory")
#define TCGEN05_RELINQ() \
    asm volatile("tcgen05.relinquish_alloc_permit.cta_group::1.sync.aligned;")
#define TCGEN05_DEALLOC(t, n) \
    asm volatile("tcgen05.dealloc.cta_group::1.sync.aligned.b32 %0, %1;" :: "r"(t), "r"((uint32_t)(n)))
#define TCGEN05_COMMIT(mbar) \
    asm volatile("tcgen05.commit.cta_group::1.mbarrier::arrive::one.shared::cluster.b64 [%0];" \
                 :: "r"((uint32_t)(mbar)) : "memory")
#define TCGEN05_FENCE_AFTER() asm volatile("tcgen05.fence::after_thread_sync;" ::: "memory")
#define TCGEN05_WAIT_LD()     asm volatile("tcgen05.wait::ld.sync.aligned;" ::: "memory")
#define FENCE_ASYNC()         asm volatile("fence.proxy.async.shared::cta;" ::: "memory")
#define MBARRIER_INIT(mbar, cnt) \
    asm volatile("mbarrier.init.shared.b64 [%0], %1;" :: "r"((uint32_t)(mbar)), "r"((uint32_t)(cnt)) : "memory")
#define MBARRIER_INVAL(mbar) \
    asm volatile("mbarrier.inval.shared.b64 [%0];" :: "r"((uint32_t)(mbar)) : "memory")

__device__ __forceinline__ void mbar_wait(uint32_t mbar, uint32_t parity) {
    uint32_t done;
    asm volatile(
        "{\n\t.reg .pred p;\n\t"
        "mbarrier.try_wait.parity.acquire.cta.shared::cta.b64 p, [%1], %2;\n\t"
        "selp.b32 %0, 1, 0, p;\n\t}"
        : "=r"(done) : "r"(mbar), "r"(parity) : "memory");
    if (!done) {
        asm volatile(
            "{\n\t.reg .pred P1;\n\t"
            "WAIT_LOOP_%=:\n\t"
            "mbarrier.try_wait.parity.acquire.cta.shared::cta.b64 P1, [%0], %1, 0x989680;\n\t"
            "@P1 bra.uni WAIT_DONE_%=;\n\t"
            "bra.uni WAIT_LOOP_%=;\n\t"
            "WAIT_DONE_%=:\n\t}"
            :: "r"(mbar), "r"(parity) : "memory");
    }
}

#define TCGEN05_LD_X32(r, ta) \
    asm volatile( \
        "tcgen05.ld.sync.aligned.32x32b.x32.b32 " \
        "{%0, %1, %2, %3, %4, %5, %6, %7, " \
        " %8, %9, %10, %11, %12, %13, %14, %15, " \
        " %16, %17, %18, %19, %20, %21, %22, %23, " \
        " %24, %25, %26, %27, %28, %29, %30, %31}, [%32];" \
        : "=r"((r)[0]),  "=r"((r)[1]),  "=r"((r)[2]),  "=r"((r)[3]), \
          "=r"((r)[4]),  "=r"((r)[5]),  "=r"((r)[6]),  "=r"((r)[7]), \
          "=r"((r)[8]),  "=r"((r)[9]),  "=r"((r)[10]), "=r"((r)[11]), \
          "=r"((r)[12]), "=r"((r)[13]), "=r"((r)[14]), "=r"((r)[15]), \
          "=r"((r)[16]), "=r"((r)[17]), "=r"((r)[18]), "=r"((r)[19]), \
          "=r"((r)[20]), "=r"((r)[21]), "=r"((r)[22]), "=r"((r)[23]), \
          "=r"((r)[24]), "=r"((r)[25]), "=r"((r)[26]), "=r"((r)[27]), \
          "=r"((r)[28]), "=r"((r)[29]), "=r"((r)[30]), "=r"((r)[31]) \
        : "r"(ta))
#define TCGEN05_LD_X16(r, ta) \
    asm volatile( \
        "tcgen05.ld.sync.aligned.32x32b.x16.b32 " \
        "{%0, %1, %2, %3, %4, %5, %6, %7, " \
        " %8, %9, %10, %11, %12, %13, %14, %15}, [%16];" \
        : "=r"((r)[0]),  "=r"((r)[1]),  "=r"((r)[2]),  "=r"((r)[3]), \
          "=r"((r)[4]),  "=r"((r)[5]),  "=r"((r)[6]),  "=r"((r)[7]), \
          "=r"((r)[8]),  "=r"((r)[9]),  "=r"((r)[10]), "=r"((r)[11]), \
          "=r"((r)[12]), "=r"((r)[13]), "=r"((r)[14]), "=r"((r)[15]) \
        : "r"(ta))
#define TCGEN05_LD_X8(r, ta) \
    asm volatile( \
        "tcgen05.ld.sync.aligned.32x32b.x8.b32 " \
        "{%0, %1, %2, %3, %4, %5, %6, %7}, [%8];" \
        : "=r"((r)[0]), "=r"((r)[1]), "=r"((r)[2]), "=r"((r)[3]), \
          "=r"((r)[4]), "=r"((r)[5]), "=r"((r)[6]), "=r"((r)[7]) \
        : "r"(ta))

// SS-mode cg1 bf16 MMA: D(TMEM) += A(smem desc) * B(smem desc)^T
__device__ __forceinline__ void mma_f16_ss(uint32_t d_tmem, uint64_t a_desc,
                                           uint64_t b_desc, uint32_t idesc,
                                           uint32_t en) {
    asm volatile(
        "{\n\t.reg .pred p;\n\t"
        "setp.ne.u32 p, %4, 0;\n\t"
        "tcgen05.mma.cta_group::1.kind::f16 [%0], %1, %2, %3, {%5, %5, %5, %5}, p;\n\t}"
        :: "r"(d_tmem), "l"(a_desc), "l"(b_desc), "r"(idesc), "r"(en), "r"(0u)
        : "memory");
}
#endif  // HAS_TCGEN05

static constexpr uint64_t SMEM_DESC_BASE_SW128 =
    (uint64_t(2) << 61) | (uint64_t(1) << 46) | (uint64_t(64) << 32) | (uint64_t(1) << 16);
#define MAKE_SMEM_DESC(a) (SMEM_DESC_BASE_SW128 | ((uint64_t)((a) >> 4) & 0x3FFF))
#define SWZ128(b) ((b) ^ (((b) >> 3) & 0x70))

// idesc: dtype F32(bit4) | atype BF16(bit7) | btype BF16(bit10) | N/8<<17 | M/16<<24
#define IDESC(NV) ((8u << 24) | (((NV) / 8u) << 17) | 0x490u)

__device__ __forceinline__ uint32_t pack_bf2(float a, float b) {
    __nv_bfloat162 p = __halves2bfloat162(__float2bfloat16(a), __float2bfloat16(b));
    return *(uint32_t*)&p;
}
__device__ __forceinline__ float2 unpack_bf2(unsigned u) {
    return __bfloat1622float2(*(__nv_bfloat162*)&u);
}

// ---------------- graph prep ----------------
// edge_index is int32 on device (JAX x64 disabled coerces int64->int32)
__global__ void k_edge_prep(const int* __restrict__ ei) {
    int e = blockIdx.x * blockDim.x + threadIdx.x;
    if (e >= NE) return;
    atomicAdd(&g_indeg[ei[NE + e]], 1);
}
// phase 1: local exclusive scan (1024/block) + block total; also emits dis
__global__ void k_scan_local() {
    __shared__ int warp_sums[32];
    const int tid = threadIdx.x;
    const int v = blockIdx.x * 1024 + tid;
    int val = (v < NN) ? g_indeg[v] : 0;
    if (v < NN) g_dis[v] = rsqrtf((float)(val + 1));   // +1 self-loop
    int x = val;
    #pragma unroll
    for (int o = 1; o < 32; o <<= 1) {
        int y = __shfl_up_sync(0xffffffffu, x, o);
        if ((tid & 31) >= o) x += y;
    }
    if ((tid & 31) == 31) warp_sums[tid >> 5] = x;
    __syncthreads();
    if (tid < 32) {
        int y = warp_sums[tid];
        #pragma unroll
        for (int o = 1; o < 32; o <<= 1) {
            int z = __shfl_up_sync(0xffffffffu, y, o);
            if (tid >= o) y += z;
        }
        warp_sums[tid] = y;
    }
    __syncthreads();
    int warp_prefix = (tid >= 32) ? warp_sums[(tid >> 5) - 1] : 0;
    if (v < NN) g_soff[v] = x + warp_prefix - val;
    if (tid == 0) g_bsum[blockIdx.x] = warp_sums[31];
}
__global__ void k_scan_bsum() {
    if (threadIdx.x == 0) {
        int run = 0;
        for (int b = 0; b < NB; b++) { int t = g_bsum[b]; g_bsum[b] = run; run += t; }
        g_soff[NN] = run;
    }
}
__global__ void k_scan_add() {
    int v = blockIdx.x * 1024 + threadIdx.x;
    if (v >= NN) return;
    int s = g_soff[v] + g_bsum[blockIdx.x];
    g_soff[v] = s;
    g_cursor[v] = s;
}
__global__ void k_scatter(const int* __restrict__ ei) {
    int e = blockIdx.x * blockDim.x + threadIdx.x;
    if (e >= NE) return;
    int r = ei[e];
    int c = ei[NE + e];
    int pos = atomicAdd(&g_cursor[c], 1);
    float nrm = g_dis[r] * g_dis[c];
    g_sedge[pos] = make_uint2((unsigned)r, __float_as_uint(nrm));
}

// ---------------- weight prep: transpose + hi/lo split + atom-linearize ---
// B operand layout [Np rows(N), Kp cols(K)], atom = 8n x 64k (1024B):
// off = (n/8 + (k/64)*(Np/8))*512 + (n%8)*64 + (k%64)
__global__ void k_prep_w(const float* __restrict__ W, __nv_bfloat16* __restrict__ hi,
                         __nv_bfloat16* __restrict__ lo, int K, int N, int Kp, int Np) {
    int idx = blockIdx.x * blockDim.x + threadIdx.x;
    if (idx >= Kp * Np) return;
    int n = idx / Kp, k = idx % Kp;
    float v = (n < N && k < K) ? W[(size_t)k * N + n] : 0.f;
    __nv_bfloat16 h = __float2bfloat16(v);
    __nv_bfloat16 l = __float2bfloat16(v - __bfloat162float(h));
    int off = ((n >> 3) + (k >> 6) * (Np >> 3)) * 512 + (n & 7) * 64 + (k & 63);
    hi[off] = h;
    lo[off] = l;
}

// ---------------- CSR aggregation (layer 1): agg1 = D^-1/2 A D^-1/2 x ------
template <int F>
__global__ void k_agg_csr(const float* __restrict__ src, float* __restrict__ dst) {
    int gtid = blockIdx.x * blockDim.x + threadIdx.x;
    int v    = gtid >> 5;
    int lane = gtid & 31;
    if (v >= NN) return;
    constexpr int NA = (F + 31) / 32;
    float acc[NA];
    float d = g_dis[v];
    const float* selfp = src + (size_t)v * F;
    #pragma unroll
    for (int i = 0; i < NA; i++) {
        int f = lane + 32 * i;
        acc[i] = (f < F) ? d * d * selfp[f] : 0.f;
    }
    int b  = g_soff[v];
    int e2 = g_soff[v + 1];
    int j = b;
    for (; j + 1 < e2; j += 2) {           // 2-edge unroll: 2x MLP
        uint2 p0 = g_sedge[j];
        uint2 p1 = g_sedge[j + 1];
        const float* s0 = src + (size_t)p0.x * F;
        const float* s1 = src + (size_t)p1.x * F;
        float w0 = __uint_as_float(p0.y);
        float w1 = __uint_as_float(p1.y);
        #pragma unroll
        for (int i = 0; i < NA; i++) {
            int f = lane + 32 * i;
            if (f < F) {
                float a0 = s0[f], a1 = s1[f];
                acc[i] += w0 * a0;
                acc[i] += w1 * a1;
            }
        }
    }
    if (j < e2) {
        uint2 pe = g_sedge[j];
        const float* sp = src + (size_t)pe.x * F;
        float w = __uint_as_float(pe.y);
        #pragma unroll
        for (int i = 0; i < NA; i++) {
            int f = lane + 32 * i;
            if (f < F) acc[i] += w * sp[f];
        }
    }
    float* dp = dst + (size_t)v * F;
    #pragma unroll
    for (int i = 0; i < NA; i++) {
        int f = lane + 32 * i;
        if (f < F) dp[f] = acc[i];
    }
}

// ---- layer-2 aggregation (bf16 h2 rows) fused with layer-3 dot:
// h3p[v] = sum_f relu(agg2[v,f] + b2[f]) * W3[f]
__global__ void k_agg2dot(const unsigned* __restrict__ src,
                          const float* __restrict__ b2,
                          const float* __restrict__ W3) {
    int gtid = blockIdx.x * blockDim.x + threadIdx.x;
    int v    = gtid >> 5;
    int lane = gtid & 31;
    if (v >= NN) return;
    const bool hiOK = lane < 18;           // words 32..49
    float2 a0 = make_float2(0.f, 0.f), a1 = make_float2(0.f, 0.f);
    float d = g_dis[v];
    float d2 = d * d;
    const unsigned* sp = src + (size_t)v * H2W;
    {
        float2 f0 = unpack_bf2(sp[lane]);
        a0.x = d2 * f0.x; a0.y = d2 * f0.y;
        if (hiOK) {
            float2 f1 = unpack_bf2(sp[32 + lane]);
            a1.x = d2 * f1.x; a1.y = d2 * f1.y;
        }
    }
    int b  = g_soff[v];
    int e2 = g_soff[v + 1];
    int j = b;
    for (; j + 1 < e2; j += 2) {
        uint2 p0 = g_sedge[j];
        uint2 p1 = g_sedge[j + 1];
        const unsigned* s0 = src + (size_t)p0.x * H2W;
        const unsigned* s1 = src + (size_t)p1.x * H2W;
        float w0 = __uint_as_float(p0.y);
        float w1 = __uint_as_float(p1.y);
        unsigned u00 = s0[lane], u10 = s1[lane];
        float2 f00 = unpack_bf2(u00), f10 = unpack_bf2(u10);
        a0.x += w0 * f00.x; a0.y += w0 * f00.y;
        a0.x += w1 * f10.x; a0.y += w1 * f10.y;
        if (hiOK) {
            unsigned u01 = s0[32 + lane], u11 = s1[32 + lane];
            float2 f01 = unpack_bf2(u01), f11 = unpack_bf2(u11);
            a1.x += w0 * f01.x; a1.y += w0 * f01.y;
            a1.x += w1 * f11.x; a1.y += w1 * f11.y;
        }
    }
    if (j < e2) {
        uint2 pe = g_sedge[j];
        const unsigned* s0 = src + (size_t)pe.x * H2W;
        float w = __uint_as_float(pe.y);
        float2 f0 = unpack_bf2(s0[lane]);
        a0.x += w * f0.x; a0.y += w * f0.y;
        if (hiOK) {
            float2 f1 = unpack_bf2(s0[32 + lane]);
            a1.x += w * f1.x; a1.y += w * f1.y;
        }
    }
    // fused bias + relu + dot(W3) + warp reduce
    int fA = 2 * lane, fB = 64 + 2 * lane;
    float s = fmaxf(a0.x + b2[fA], 0.f) * W3[fA]
            + fmaxf(a0.y + b2[fA + 1], 0.f) * W3[fA + 1];
    if (hiOK)
        s += fmaxf(a1.x + b2[fB], 0.f) * W3[fB]
           + fmaxf(a1.y + b2[fB + 1], 0.f) * W3[fB + 1];
    #pragma unroll
    for (int o = 16; o > 0; o >>= 1)
        s += __shfl_xor_sync(0xffffffffu, s, o);
    if (lane == 0) g_h3p[v] = s;
}

// ================= Fused layer-1+2 tensor GEMM ============================
// Per CTA (128 rows):
//   D1 = agg1_tile @ W1 (TMEM 0..303)   [split-bf16, 3 products]
//   h1  = relu(D1 + b1) split hi/lo -> double-buffered A2 smem (no DRAM)
//   D2 += h1_chunk @ W2_chunk (TMEM 320..423), epilogue(c+1) overlaps MMA(c)
//   h2  = bf16(D2) -> g_h2b (packed bf16x2 rows)
// smem (199680 B):
//   ctrl @0 | A2hi0 @1024 | A2lo0 @17408 | A2hi1 @33792 | A2lo1 @50176
//   B2hi @66560 (66560) | B2lo @133120 (66560)
//   phase-1 aliases inside B2 region (dead before B2 fill):
//   A1hi @66560 | A1lo @82944 | B1hi @99328 | B1lo @138240
#define F_A2HI0 1024
#define F_A2LO0 17408
#define F_A2HI1 33792
#define F_A2LO1 50176
#define F_B2HI  66560
#define F_B2LO  133120
#define F_A1HI  66560
#define F_A1LO  82944
#define F_B1HI  99328
#define F_B1LO  138240
#define SMEMF   199680

__global__ void __launch_bounds__(256, 1)
k_tgemm12(const float* __restrict__ A, const float* __restrict__ b1,
          unsigned* __restrict__ Cout) {
#if HAS_TCGEN05
    extern __shared__ char smem[];
    uint32_t sb = smem_to_u32(smem);
    int tid = threadIdx.x, wid = tid >> 5, lane = tid & 31;
    int brow = blockIdx.x * 128;

    if (wid == 0) { TCGEN05_ALLOC(sb + 0, 512); TCGEN05_RELINQ(); }
    if (tid == 0) MBARRIER_INIT(sb + 8, 1);
    __syncthreads();
    uint32_t tb = *(volatile uint32_t*)smem;
    const uint32_t tD1 = tb, tD2 = tb + 320;

    // ---- phase 1 fills ----
    for (int i = tid; i < 128 * 64; i += 256) {
        int m = i >> 6, k = i & 63;
        int gm = brow + m;
        float v = (gm < NN && k < F0) ? A[(size_t)gm * F0 + k] : 0.f;
        __nv_bfloat16 h = __float2bfloat16(v);
        __nv_bfloat16 l = __float2bfloat16(v - __bfloat162float(h));
        uint32_t sw = SWZ128((uint32_t)((m << 7) + (k << 1)));
        *(__nv_bfloat16*)(smem + F_A1HI + sw) = h;
        *(__nv_bfloat16*)(smem + F_A1LO + sw) = l;
    }
    for (int i = tid; i < (L1_NP * L1_KP) / 8; i += 256) {
        uint4 h = ((const uint4*)g_w1hi)[i];
        uint4 l = ((const uint4*)g_w1lo)[i];
        uint32_t sw = SWZ128((uint32_t)(i * 16));
        *(uint4*)(smem + F_B1HI + sw) = h;
        *(uint4*)(smem + F_B1LO + sw) = l;
    }
    FENCE_ASYNC();
    __syncthreads();

    // ---- MMA1 (commit idx 0) ----
    if (wid == 0 && elect_one_pred()) {
        uint64_t ah = MAKE_SMEM_DESC(sb + F_A1HI);
        uint64_t al = MAKE_SMEM_DESC(sb + F_A1LO);
        uint64_t bh = MAKE_SMEM_DESC(sb + F_B1HI);
        uint64_t bl = MAKE_SMEM_DESC(sb + F_B1LO);
        const uint32_t id0 = IDESC(256), id1 = IDESC(48);
        #pragma unroll
        for (int s = 0; s < 4; s++) {
            uint32_t en = (s > 0);
            mma_f16_ss(tD1,       ah + 2 * s, bh + 2 * s,        id0, en);
            mma_f16_ss(tD1 + 256, ah + 2 * s, bh + 2048 + 2 * s, id1, en);
            mma_f16_ss(tD1,       ah + 2 * s, bl + 2 * s,        id0, 1);
            mma_f16_ss(tD1 + 256, ah + 2 * s, bl + 2048 + 2 * s, id1, 1);
            mma_f16_ss(tD1,       al + 2 * s, bh + 2 * s,        id0, 1);
            mma_f16_ss(tD1 + 256, al + 2 * s, bh + 2048 + 2 * s, id1, 1);
        }
        TCGEN05_COMMIT(sb + 8);
    }
    mbar_wait(sb + 8, 0);           // wait commit 0 (parity 0)
    TCGEN05_FENCE_AFTER();
    __syncthreads();                // A1/B1 dead from here

    // ---- B2 fill (overwrites phase-1 region) ----
    for (int i = tid; i < (L2_NP * L2_KP) / 8; i += 256) {
        uint4 h = ((const uint4*)g_w2hi)[i];
        uint4 l = ((const uint4*)g_w2lo)[i];
        uint32_t sw = SWZ128((uint32_t)(i * 16));
        *(uint4*)(smem + F_B2HI + sw) = h;
        *(uint4*)(smem + F_B2LO + sw) = l;
    }

    // ---- pipelined chunk loop (double-buffered A2) ----
    // commit idx for chunk c = c+1. Epilogue of chunk c (c>=2) waits commit
    // idx c-1 (chunk c-2 done reading buffer c&1). Waits alternate parity
    // strictly: p0(idx0 above), p1, p0, p1, p0, p1 — one wait per commit.
    const uint64_t a2h[2] = { MAKE_SMEM_DESC(sb + F_A2HI0), MAKE_SMEM_DESC(sb + F_A2HI1) };
    const uint64_t a2l[2] = { MAKE_SMEM_DESC(sb + F_A2LO0), MAKE_SMEM_DESC(sb + F_A2LO1) };
    const uint64_t b2h = MAKE_SMEM_DESC(sb + F_B2HI);
    const uint64_t b2l = MAKE_SMEM_DESC(sb + F_B2LO);
    const uint32_t id2 = IDESC(104);

    for (int c = 0; c < 5; c++) {
        if (c >= 2) mbar_wait(sb + 8, (uint32_t)((c - 1) & 1));  // idx c-1
        const int buf = c & 1;
        char* a2hi_p = smem + F_A2HI0 + buf * 32768;
        char* a2lo_p = smem + F_A2LO0 + buf * 32768;
        if (wid < 4) {
            int row = wid * 32 + lane;
            uint32_t r[64];
            if (c < 4) {
                TCGEN05_LD_X32(r,      tD1 + 64 * c);
                TCGEN05_LD_X32(r + 32, tD1 + 64 * c + 32);
            } else {
                TCGEN05_LD_X32(r,      tD1 + 256);
                TCGEN05_LD_X16(r + 32, tD1 + 288);
            }
            TCGEN05_WAIT_LD();
            #pragma unroll
            for (int j = 0; j < 64; j += 2) {
                int gc = 64 * c + j;
                float v0 = (gc     < F1) ? fmaxf(__uint_as_float(r[j])     + b1[gc],     0.f) : 0.f;
                float v1 = (gc + 1 < F1) ? fmaxf(__uint_as_float(r[j + 1]) + b1[gc + 1], 0.f) : 0.f;
                __nv_bfloat16 h0 = __float2bfloat16(v0);
                __nv_bfloat16 h1b = __float2bfloat16(v1);
                __nv_bfloat16 l0 = __float2bfloat16(v0 - __bfloat162float(h0));
                __nv_bfloat16 l1 = __float2bfloat16(v1 - __bfloat162float(h1b));
                __nv_bfloat162 ph = __halves2bfloat162(h0, h1b);
                __nv_bfloat162 pl = __halves2bfloat162(l0, l1);
                uint32_t sw = SWZ128((uint32_t)((row << 7) + (j << 1)));
                *(uint32_t*)(a2hi_p + sw) = *(uint32_t*)&ph;
                *(uint32_t*)(a2lo_p + sw) = *(uint32_t*)&pl;
            }
        }
        FENCE_ASYNC();
        __syncthreads();   // A2[buf] ready; also covers B2 fill before chunk 0

        if (wid == 0 && elect_one_pred()) {
            uint32_t boff = c * 832;   // atom-col stride: 13 atoms * 1024B / 16
            #pragma unroll
            for (int s = 0; s < 4; s++) {
                uint32_t aoff = 2 * s, ko = boff + 2 * s;
                mma_f16_ss(tD2, a2h[buf] + aoff, b2h + ko, id2, (c > 0 || s > 0) ? 1u : 0u);
                mma_f16_ss(tD2, a2h[buf] + aoff, b2l + ko, id2, 1);
                mma_f16_ss(tD2, a2l[buf] + aoff, b2h + ko, id2, 1);
            }
            TCGEN05_COMMIT(sb + 8);    // commit idx c+1
        }
        // no wait here — next epilogue writes the other buffer
    }
    mbar_wait(sb + 8, 0);   // commit idx 4 (chunk 3)
    mbar_wait(sb + 8, 1);   // commit idx 5 (chunk 4)
    TCGEN05_FENCE_AFTER();
    __syncthreads();

    // ---- final epilogue: D2 -> packed bf16x2 rows -> g_h2b ----
    uint32_t* stg = (uint32_t*)(smem + 1024);   // 128 x H2W u32 (A2 region dead)
    if (wid < 4) {
        int row = wid * 32 + lane;
        uint32_t r[32];
        #pragma unroll
        for (int g = 0; g < 3; g++) {
            TCGEN05_LD_X32(r, tD2 + g * 32);
            TCGEN05_WAIT_LD();
            #pragma unroll
            for (int j = 0; j < 32; j += 2) {
                int w = (g * 32 + j) >> 1;
                stg[row * H2W + w] = pack_bf2(__uint_as_float(r[j]),
                                              __uint_as_float(r[j + 1]));
            }
        }
        TCGEN05_LD_X8(r, tD2 + 96);
        TCGEN05_WAIT_LD();
        stg[row * H2W + 48] = pack_bf2(__uint_as_float(r[0]), __uint_as_float(r[1]));
        stg[row * H2W + 49] = pack_bf2(__uint_as_float(r[2]), __uint_as_float(r[3]));
    }
    __syncthreads();
    for (int i = tid; i < 128 * 50; i += 256) {
        int m = i / 50, w = i - m * 50;
        int gm = brow + m;
        if (gm < NN) Cout[(size_t)gm * H2W + w] = stg[m * H2W + w];
    }
    __syncthreads();
    if (tid == 0) MBARRIER_INVAL(sb + 8);
    __syncthreads();
    if (wid == 0) TCGEN05_DEALLOC(tb, 512);
#endif
}

// ---------------- final output: CSR aggregate of h3p ----------------------
__global__ void k_out_csr(float* __restrict__ out, const float* __restrict__ b3) {
    int v = blockIdx.x * blockDim.x + threadIdx.x;
    if (v >= NN) return;
    float d = g_dis[v];
    float s = d * d * g_h3p[v];
    int b  = g_soff[v];
    int e2 = g_soff[v + 1];
    for (int j = b; j < e2; j++) {
        uint2 pe = g_sedge[j];
        s += __uint_as_float(pe.y) * g_h3p[pe.x];
    }
    out[v] = s + b3[0];
}

// ---------------- launch ----------------
extern "C" void kernel_launch(void* const* d_in, const int* in_sizes, int n_in,
                              void* d_out, int out_size) {
    const float* x  = (const float*)d_in[0];
    const int*   ei = (const int*)d_in[1];
    const float* W1 = (const float*)d_in[2];
    const float* b1 = (const float*)d_in[3];
    const float* W2 = (const float*)d_in[4];
    const float* b2 = (const float*)d_in[5];
    const float* W3 = (const float*)d_in[6];
    const float* b3 = (const float*)d_in[7];
    float* out = (float*)d_out;

    const int T = 256;
    float*    agg1 = nullptr; cudaGetSymbolAddress((void**)&agg1, g_agg1);
    unsigned* h2b  = nullptr; cudaGetSymbolAddress((void**)&h2b,  g_h2b);
    int*      degp = nullptr; cudaGetSymbolAddress((void**)&degp, g_indeg);
    __nv_bfloat16 *w1h, *w1l, *w2h, *w2l;
    cudaGetSymbolAddress((void**)&w1h, g_w1hi);
    cudaGetSymbolAddress((void**)&w1l, g_w1lo);
    cudaGetSymbolAddress((void**)&w2h, g_w2hi);
    cudaGetSymbolAddress((void**)&w2l, g_w2lo);

    cudaFuncSetAttribute(k_tgemm12, cudaFuncAttributeMaxDynamicSharedMemorySize, SMEMF);

    // weight prep (graph-independent)
    k_prep_w<<<(L1_NP * L1_KP + T - 1) / T, T>>>(W1, w1h, w1l, F0, F1, L1_KP, L1_NP);
    k_prep_w<<<(L2_NP * L2_KP + T - 1) / T, T>>>(W2, w2h, w2l, F1, F2, L2_KP, L2_NP);

    // CSR build
    cudaMemsetAsync(degp, 0, NN * sizeof(int));
    k_edge_prep<<<(NE + T - 1) / T, T>>>(ei);
    k_scan_local<<<NB, 1024>>>();
    k_scan_bsum<<<1, 32>>>();
    k_scan_add<<<NB, 1024>>>();
    k_scatter<<<(NE + T - 1) / T, T>>>(ei);

    const unsigned aggGrid = (unsigned)(((long long)NN * 32 + T - 1) / T);

    // Layers 1+2 fused: aggregate(58) -> [GEMM1 + bias/relu + GEMM2] -> h2b
    k_agg_csr<F0><<<aggGrid, T>>>(x, agg1);
    k_tgemm12<<<MTILES, 256, SMEMF>>>(agg1, b1, h2b);

    // Layer-2 aggregation (bf16 gather) fused with layer-3 dot, then output
    k_agg2dot<<<aggGrid, T>>>(h2b, b2, W3);
    k_out_csr<<<(NN + T - 1) / T, T>>>(out, b3);

    (void)in_sizes; (void)n_in; (void)out_size;
}